// round 13
// baseline (speedup 1.0000x reference)
#include <cuda_runtime.h>
#include <cuda_fp16.h>
#include <math.h>
#include <stdint.h>

#define NN 20000
#define NG 400
#define KNB 12
#define NE 240000
#define NL 4

// ---- packed fp16 weight region offsets (halves) ----
#define HK_EW2 0
#define HK_CW1 65536
#define HK_NW2 131072
#define HK_NW1 196608
#define HK_NE  393216
#define HK_WP  413696
#define HK_TOTAL 675840

// ---- static device scratch ----
__device__ float g_temb[NG * 128];
__device__ float g_h[NN * 128];
__device__ float g_X[NN * 256];      // [h | t]
__device__ float g_P[NN * 256];
__device__ __half g_M[NE * 128];     // fp16 messages
__device__ float g_u[NN * 128];
__device__ __half g_packWh[HK_TOTAL];
__device__ float g_biasP[NL * 256];
__device__ float g_shift[NN * 3];

__device__ __forceinline__ float silu_f(float x) {
    return __fdividef(x, 1.0f + __expf(-x));
}
__device__ __forceinline__ uint32_t f2h2(float a, float b) {
    __half2 h = __floats2half2_rn(a, b);
    return *(uint32_t*)&h;
}

__device__ __forceinline__ void mma_f16(float c[4], uint32_t a0, uint32_t a1,
                                        uint32_t a2, uint32_t a3,
                                        uint32_t b0, uint32_t b1) {
    asm volatile(
        "mma.sync.aligned.m16n8k16.row.col.f32.f16.f16.f32 "
        "{%0,%1,%2,%3}, {%4,%5,%6,%7}, {%8,%9}, {%0,%1,%2,%3};"
        : "+f"(c[0]), "+f"(c[1]), "+f"(c[2]), "+f"(c[3])
        : "r"(a0), "r"(a1), "r"(a2), "r"(a3), "r"(b0), "r"(b1));
}

__device__ __forceinline__ void cp16(uint32_t saddr, const void* g) {
    asm volatile("cp.async.ca.shared.global [%0], [%1], 16;" :: "r"(saddr), "l"(g));
}
#define CP_COMMIT() asm volatile("cp.async.commit_group;" ::: "memory")
#define CP_WAIT1()  asm volatile("cp.async.wait_group 1;" ::: "memory")
#define CP_WAIT0()  asm volatile("cp.async.wait_group 0;" ::: "memory")

// fp16 B fragment layout per 32-K block (4096 halves): pos = (nf*32+lane)*8 + q
//   k = kb*32 + (q>>1)*8 + (lane&3)*2 + (q&1) ; n = nf*8 + (lane>>2)

// ================= launch 0: setup = pack + temb =================
__global__ void setup_kernel(const float* __restrict__ eW2, const float* __restrict__ cW1,
                             const float* __restrict__ nW2, const float* __restrict__ nW1,
                             const float* __restrict__ neW, const float* __restrict__ eW1,
                             const float* __restrict__ eb1,
                             const float* __restrict__ t,
                             const float* __restrict__ tmW1, const float* __restrict__ tmb1,
                             const float* __restrict__ tmW2, const float* __restrict__ tmb2) {
    int f = blockIdx.y;
    int tid = threadIdx.x;

    if (f == 6) {                       // ---- time-embedding MLP ----
        int g = blockIdx.x;
        if (g >= NG) return;
        __shared__ float e[128];
        __shared__ float hid[256];
        float tv = t[g];
        if (tid < 64) {
            float fr = expf(-(float)tid * (logf(10000.0f) / 63.0f));
            float a = tv * fr;
            e[tid] = sinf(a); e[tid + 64] = cosf(a);
        }
        __syncthreads();
        {
            float s = tmb1[tid];
            #pragma unroll 4
            for (int k = 0; k < 128; k++) s = fmaf(e[k], tmW1[k * 256 + tid], s);
            hid[tid] = silu_f(s);
        }
        __syncthreads();
        if (tid < 128) {
            float s = tmb2[tid];
            #pragma unroll 4
            for (int k = 0; k < 256; k++) s = fmaf(hid[k], tmW2[k * 128 + tid], s);
            g_temb[g * 128 + tid] = s;
        }
        return;
    }

    int i = blockIdx.x * 256 + tid;

    if (f == 5) {                       // ---- folded eW1 -> Wp (fp16) ----
        if (i >= 262144) return;
        int l = i >> 16, r = i & 65535, slab = r >> 15, r2 = r & 32767;
        int kb = r2 >> 12, rr = r2 & 4095;
        int q = rr & 7, lane = (rr >> 3) & 31, nf = rr >> 8;
        int k = kb * 32 + (q >> 1) * 8 + (lane & 3) * 2 + (q & 1);
        int n = nf * 8 + (lane >> 2);
        const float* W = eW1 + (size_t)l * 385 * 128;
        float v;
        if (slab == 0) v = (k < 128) ? W[k * 128 + n] : W[(257 + (k - 128)) * 128 + n];
        else           v = (k < 128) ? W[(128 + k) * 128 + n] : 0.f;
        g_packWh[HK_WP + (l * 2 + slab) * 32768 + kb * 4096 + rr] = __float2half(v);
        return;
    }

    int kb, rr, dstbase;
    const float* src = nullptr;
    if (f == 0) {                       // eW2 + cW1
        if (i >= 131072) return;
        int mat = i >> 16, r16 = i & 65535;
        int l = r16 >> 14, r14 = r16 & 16383;
        kb = r14 >> 12; rr = r14 & 4095;
        src = (mat == 0 ? eW2 : cW1) + (size_t)l * 16384;
        dstbase = (mat == 0 ? HK_EW2 : HK_CW1) + l * 16384;
    } else if (f == 1) {                // nW2
        if (i >= 65536) return;
        int l = i >> 14, r14 = i & 16383;
        kb = r14 >> 12; rr = r14 & 4095;
        src = nW2 + (size_t)l * 16384;
        dstbase = HK_NW2 + l * 16384;
    } else if (f == 2) {
        return;
    } else if (f == 3) {                // nW1
        if (i >= 196608) return;
        int l = i / 49152, r = i % 49152;
        kb = r >> 12; rr = r & 4095;
        src = nW1 + (size_t)l * 49152;
        dstbase = HK_NW1 + l * 49152;
    } else {                            // f == 4: ne + biasP
        if (i >= 20480) {
            if (i < 21504) {
                int idx2 = i - 20480;
                int l = idx2 >> 8, c = idx2 & 255;
                g_biasP[l * 256 + c] = (c < 128) ? eb1[l * 128 + c] : 0.f;
            }
            return;
        }
        kb = i >> 12; rr = i & 4095;
        src = neW;
        dstbase = HK_NE;
    }
    int q = rr & 7, lane = (rr >> 3) & 31, nf = rr >> 8;
    int k = kb * 32 + (q >> 1) * 8 + (lane & 3) * 2 + (q & 1);
    int n = nf * 8 + (lane >> 2);
    g_packWh[dstbase + kb * 4096 + rr] = __float2half(src[(size_t)k * 128 + n]);
}

// ================= pipelined node GEMM (fp16 m16n8k16) =================
// MODE 0: plain A0[M,ldA]; MODE 1: ne ([z|spemb] + prologue); MODE 2: MI ([h|sum12 m|t])
template <int NS, int MODE, bool SILU, bool RES, bool DUAL>
__global__ void __launch_bounds__(256) mma_node(
    const float* __restrict__ A0, const void* __restrict__ A1v,
    const float* __restrict__ A2, const int* __restrict__ idxp,
    const int* __restrict__ batch, int ldA,
    const __half* __restrict__ W0, const __half* __restrict__ W1,
    const float* __restrict__ bias,
    float* __restrict__ C, int ldC, float* __restrict__ C2, int ldC2,
    int M, int Kb, const float* __restrict__ Rsrc) {
    extern __shared__ char smc[];
    __half* Ah  = (__half*)smc;                         // 128 x 40 halves = 10240 B
    __half* Bsh = (__half*)(smc + 10240);               // 2 x NS*4096 halves
    float* s_bias = (float*)(smc + 10240 + NS * 16384);
    int tid = threadIdx.x, w = tid >> 5, lane = tid & 31;
    for (int i = tid; i < NS * 128; i += 256) s_bias[i] = bias[i];
    int m0 = blockIdx.x * 128;
    uint32_t bsh_sm = (uint32_t)__cvta_generic_to_shared(Bsh);

    if (MODE == 1) {
        for (int idx = tid; idx < 4096; idx += 256) {
            int r = idx >> 5, c4 = idx & 31;
            int row = m0 + r;
            if (row < NN) {
                float4 tv = *(const float4*)(g_temb + (size_t)batch[row] * 128 + c4 * 4);
                *(float4*)(g_X + (size_t)row * 256 + 128 + c4 * 4) = tv;
            }
        }
        if (tid < 128) {
            int row = m0 + tid;
            if (row < NN) {
                g_shift[row * 3 + 0] = 0.f;
                g_shift[row * 3 + 1] = 0.f;
                g_shift[row * 3 + 2] = 0.f;
            }
        }
    }

    float acc[NS][16][4];
    #pragma unroll
    for (int s = 0; s < NS; s++)
        #pragma unroll
        for (int nf = 0; nf < 16; nf++)
            #pragma unroll
            for (int j = 0; j < 4; j++) acc[s][nf][j] = 0.f;

    uint4 av[2];
    auto ldA_regs = [&](int kb) {
        #pragma unroll
        for (int i = 0; i < 2; i++) {
            int idx = tid + i * 256;
            int r = idx >> 2, c8 = (idx & 3) * 8;
            int row = m0 + r;
            float f[8];
            #pragma unroll
            for (int j = 0; j < 8; j++) f[j] = 0.f;
            if (row < M) {
                if (MODE == 0) {
                    const float* p = A0 + (size_t)row * ldA + kb * 32 + c8;
                    float4 x0 = *(const float4*)p, x1 = *(const float4*)(p + 4);
                    f[0]=x0.x; f[1]=x0.y; f[2]=x0.z; f[3]=x0.w;
                    f[4]=x1.x; f[5]=x1.y; f[6]=x1.z; f[7]=x1.w;
                } else if (MODE == 1) {
                    const float* p = (kb < 4)
                        ? A0 + (size_t)row * 128 + kb * 32 + c8
                        : (const float*)A1v + (size_t)idxp[row] * 32 + c8;
                    float4 x0 = *(const float4*)p, x1 = *(const float4*)(p + 4);
                    f[0]=x0.x; f[1]=x0.y; f[2]=x0.z; f[3]=x0.w;
                    f[4]=x1.x; f[5]=x1.y; f[6]=x1.z; f[7]=x1.w;
                } else {
                    if (kb < 4 || kb >= 8) {
                        const float* p = (kb < 4)
                            ? A0 + (size_t)row * 128 + kb * 32 + c8
                            : A2 + (size_t)row * 256 + (kb - 8) * 32 + c8;
                        float4 x0 = *(const float4*)p, x1 = *(const float4*)(p + 4);
                        f[0]=x0.x; f[1]=x0.y; f[2]=x0.z; f[3]=x0.w;
                        f[4]=x1.x; f[5]=x1.y; f[6]=x1.z; f[7]=x1.w;
                    } else {
                        const __half* base = (const __half*)A1v
                            + (size_t)row * KNB * 128 + (kb - 4) * 32 + c8;
                        #pragma unroll
                        for (int j = 0; j < KNB; j++) {
                            uint4 u = *(const uint4*)(base + (size_t)j * 128);
                            float2 p0 = __half22float2(*(__half2*)&u.x);
                            float2 p1 = __half22float2(*(__half2*)&u.y);
                            float2 p2 = __half22float2(*(__half2*)&u.z);
                            float2 p3 = __half22float2(*(__half2*)&u.w);
                            f[0]+=p0.x; f[1]+=p0.y; f[2]+=p1.x; f[3]+=p1.y;
                            f[4]+=p2.x; f[5]+=p2.y; f[6]+=p3.x; f[7]+=p3.y;
                        }
                    }
                }
            }
            av[i].x = f2h2(f[0], f[1]); av[i].y = f2h2(f[2], f[3]);
            av[i].z = f2h2(f[4], f[5]); av[i].w = f2h2(f[6], f[7]);
        }
    };
    auto stA = [&]() {
        #pragma unroll
        for (int i = 0; i < 2; i++) {
            int idx = tid + i * 256;
            int r = idx >> 2, c8 = (idx & 3) * 8;
            *(uint4*)(Ah + r * 40 + c8) = av[i];
        }
    };
    auto cpB = [&](int kb, int buf) {
        uint32_t dst = bsh_sm + buf * (NS * 8192);
        const __half* s0 = W0 + (size_t)kb * 4096;
        #pragma unroll
        for (int j = 0; j < 2; j++)
            cp16(dst + (tid + j * 256) * 16, s0 + (tid + j * 256) * 8);
        if constexpr (NS == 2) {
            const __half* s1 = W1 + (size_t)kb * 4096;
            #pragma unroll
            for (int j = 0; j < 2; j++)
                cp16(dst + 8192 + (tid + j * 256) * 16, s1 + (tid + j * 256) * 8);
        }
        CP_COMMIT();
    };

    ldA_regs(0);
    cpB(0, 0);
    for (int kb = 0; kb < Kb; kb++) {
        int cur = kb & 1;
        stA();
        if (kb + 1 < Kb) {
            cpB(kb + 1, cur ^ 1);
            ldA_regs(kb + 1);
            CP_WAIT1();
        } else {
            CP_WAIT0();
        }
        __syncthreads();
        const __half* Bb = Bsh + cur * (NS * 4096);
        uint32_t Areg[2][4];
        const __half* ap = Ah + (w * 16 + (lane >> 2)) * 40 + (lane & 3) * 2;
        #pragma unroll
        for (int ks = 0; ks < 2; ks++) {
            const __half* p = ap + ks * 16;
            Areg[ks][0] = *(const uint32_t*)(p);
            Areg[ks][1] = *(const uint32_t*)(p + 8 * 40);
            Areg[ks][2] = *(const uint32_t*)(p + 8);
            Areg[ks][3] = *(const uint32_t*)(p + 8 * 40 + 8);
        }
        #pragma unroll
        for (int nf = 0; nf < 16; nf++) {
            uint4 bv = *(const uint4*)(Bb + (nf * 32 + lane) * 8);
            mma_f16(acc[0][nf], Areg[0][0], Areg[0][1], Areg[0][2], Areg[0][3], bv.x, bv.y);
            mma_f16(acc[0][nf], Areg[1][0], Areg[1][1], Areg[1][2], Areg[1][3], bv.z, bv.w);
            if constexpr (NS == 2) {
                uint4 b1v = *(const uint4*)(Bb + 4096 + (nf * 32 + lane) * 8);
                mma_f16(acc[1][nf], Areg[0][0], Areg[0][1], Areg[0][2], Areg[0][3], b1v.x, b1v.y);
                mma_f16(acc[1][nf], Areg[1][0], Areg[1][1], Areg[1][2], Areg[1][3], b1v.z, b1v.w);
            }
        }
        __syncthreads();
    }

    int r0 = w * 16 + (lane >> 2);
    int row0 = m0 + r0, row1 = row0 + 8;
    #pragma unroll
    for (int s = 0; s < NS; s++) {
        #pragma unroll
        for (int nf = 0; nf < 16; nf++) {
            int lc = nf * 8 + (lane & 3) * 2;
            int col = s * 128 + lc;
            float v0 = acc[s][nf][0] + s_bias[col];
            float v1 = acc[s][nf][1] + s_bias[col + 1];
            float v2 = acc[s][nf][2] + s_bias[col];
            float v3 = acc[s][nf][3] + s_bias[col + 1];
            if (SILU) { v0 = silu_f(v0); v1 = silu_f(v1); v2 = silu_f(v2); v3 = silu_f(v3); }
            if (row0 < M) {
                if (RES) {
                    float2 r = *(const float2*)(Rsrc + (size_t)row0 * 128 + col);
                    v0 += r.x; v1 += r.y;
                }
                *(float2*)(C + (size_t)row0 * ldC + col) = make_float2(v0, v1);
                if (DUAL) *(float2*)(C2 + (size_t)row0 * ldC2 + col) = make_float2(v0, v1);
            }
            if (row1 < M) {
                if (RES) {
                    float2 r = *(const float2*)(Rsrc + (size_t)row1 * 128 + col);
                    v2 += r.x; v3 += r.y;
                }
                *(float2*)(C + (size_t)row1 * ldC + col) = make_float2(v2, v3);
                if (DUAL) *(float2*)(C2 + (size_t)row1 * ldC2 + col) = make_float2(v2, v3);
            }
        }
    }
}
#define NODE_SMEM1 27136
#define NODE_SMEM2 44032

// ================= fused edge kernel (fp16, unchanged from R12) =================
#define EDGE_SMEM 31232
__global__ void __launch_bounds__(256, 2) mma_edge(
    const int* __restrict__ esrc, const int* __restrict__ edst,
    const float* __restrict__ coords, const float* __restrict__ P,
    const float* __restrict__ wc, const float* __restrict__ eb2,
    const __half* __restrict__ w2pk, const __half* __restrict__ c1pk,
    const float* __restrict__ cb1, const float* __restrict__ cw2) {
    extern __shared__ char smc[];
    __half* Ah    = (__half*)smc;                 // 128 x 40 halves
    __half* Bsh   = (__half*)(smc + 10240);       // 2 x 4096 halves
    float* s_gate = (float*)(smc + 26624);        // 256
    int* s_src    = (int*)(smc + 27648);
    int* s_dst    = (int*)(smc + 28160);
    float* s_ds   = (float*)(smc + 28672);
    float* s_wc   = (float*)(smc + 29184);
    float* s_eb2  = (float*)(smc + 29696);
    float* s_cb1  = (float*)(smc + 30208);
    float* s_cw2  = (float*)(smc + 30720);
    int tid = threadIdx.x, w = tid >> 5, lane = tid & 31;
    int wr = w & 3, cg = w >> 2;
    uint32_t bsh_sm = (uint32_t)__cvta_generic_to_shared(Bsh);
    int ebase = blockIdx.x * 128;

    auto cpBh = [&](const __half* src, int buf) {
        uint32_t dst = bsh_sm + buf * 8192;
        #pragma unroll
        for (int j = 0; j < 2; j++)
            cp16(dst + (tid + j * 256) * 16, src + (tid + j * 256) * 8);
        CP_COMMIT();
    };

    cpBh(w2pk, 0);

    if (tid < 128) {
        int e = ebase + tid;
        int s = esrc[e], d = edst[e];
        s_src[tid] = s; s_dst[tid] = d;
        float dx = coords[s * 3 + 0] - coords[d * 3 + 0];
        float dy = coords[s * 3 + 1] - coords[d * 3 + 1];
        float dz = coords[s * 3 + 2] - coords[d * 3 + 2];
        s_ds[tid] = dx * dx + dy * dy + dz * dz;
        s_wc[tid] = wc[tid];
        s_eb2[tid] = eb2[tid];
        s_cb1[tid] = cb1[tid];
        s_cw2[tid] = cw2[tid];
    }
    __syncthreads();

    uint4 av[2];
    auto ldA1 = [&](int kb) {
        #pragma unroll
        for (int i = 0; i < 2; i++) {
            int idx = tid + i * 256;
            int r = idx >> 2, c8 = idx & 3;
            int s = s_src[r], d = s_dst[r];
            float ds = s_ds[r];
            const float* Pp = P + (size_t)s * 256 + kb * 32 + c8 * 8;
            const float* Pq = P + (size_t)d * 256 + 128 + kb * 32 + c8 * 8;
            const float* Wv = s_wc + kb * 32 + c8 * 8;
            float4 a0 = *(const float4*)Pp, a1 = *(const float4*)(Pp + 4);
            float4 b0 = *(const float4*)Pq, b1 = *(const float4*)(Pq + 4);
            float4 w0 = *(const float4*)Wv, w1 = *(const float4*)(Wv + 4);
            float v0 = silu_f(a0.x + b0.x + ds * w0.x);
            float v1 = silu_f(a0.y + b0.y + ds * w0.y);
            float v2 = silu_f(a0.z + b0.z + ds * w0.z);
            float v3 = silu_f(a0.w + b0.w + ds * w0.w);
            float v4 = silu_f(a1.x + b1.x + ds * w1.x);
            float v5 = silu_f(a1.y + b1.y + ds * w1.y);
            float v6 = silu_f(a1.z + b1.z + ds * w1.z);
            float v7 = silu_f(a1.w + b1.w + ds * w1.w);
            av[i].x = f2h2(v0, v1); av[i].y = f2h2(v2, v3);
            av[i].z = f2h2(v4, v5); av[i].w = f2h2(v6, v7);
        }
    };
    auto ldA2 = [&](int kb) {
        #pragma unroll
        for (int i = 0; i < 2; i++) {
            int idx = tid + i * 256;
            int r = idx >> 2, c8 = idx & 3;
            av[i] = *(const uint4*)(g_M + (size_t)(ebase + r) * 128 + kb * 32 + c8 * 8);
        }
    };
    auto stA = [&]() {
        #pragma unroll
        for (int i = 0; i < 2; i++) {
            int idx = tid + i * 256;
            int r = idx >> 2, c8 = idx & 3;
            *(uint4*)(Ah + r * 40 + c8 * 8) = av[i];
        }
    };

    float acc[2][8][4];
    #pragma unroll
    for (int mf = 0; mf < 2; mf++)
        #pragma unroll
        for (int nf = 0; nf < 8; nf++)
            #pragma unroll
            for (int j = 0; j < 4; j++) acc[mf][nf][j] = 0.f;

    auto gemm_block = [&](const __half* Bb) {
        uint32_t Areg[2][2][4];
        const __half* ap = Ah + (wr * 32 + (lane >> 2)) * 40 + (lane & 3) * 2;
        #pragma unroll
        for (int mf = 0; mf < 2; mf++) {
            const __half* base = ap + mf * 16 * 40;
            #pragma unroll
            for (int ks = 0; ks < 2; ks++) {
                const __half* p = base + ks * 16;
                Areg[mf][ks][0] = *(const uint32_t*)(p);
                Areg[mf][ks][1] = *(const uint32_t*)(p + 8 * 40);
                Areg[mf][ks][2] = *(const uint32_t*)(p + 8);
                Areg[mf][ks][3] = *(const uint32_t*)(p + 8 * 40 + 8);
            }
        }
        #pragma unroll
        for (int nf = 0; nf < 8; nf++) {
            uint4 bv = *(const uint4*)(Bb + ((cg * 8 + nf) * 32 + lane) * 8);
            #pragma unroll
            for (int mf = 0; mf < 2; mf++) {
                mma_f16(acc[mf][nf], Areg[mf][0][0], Areg[mf][0][1], Areg[mf][0][2], Areg[mf][0][3],
                        bv.x, bv.y);
                mma_f16(acc[mf][nf], Areg[mf][1][0], Areg[mf][1][1], Areg[mf][1][2], Areg[mf][1][3],
                        bv.z, bv.w);
            }
        }
    };

    // ---- GEMM 1: pre @ eW2 ----
    ldA1(0);
    #pragma unroll
    for (int kb = 0; kb < 4; kb++) {
        stA();
        if (kb < 3) {
            cpBh(w2pk + (size_t)(kb + 1) * 4096, (kb + 1) & 1);
            ldA1(kb + 1);
        } else {
            cpBh(c1pk, 0);
        }
        CP_WAIT1();
        __syncthreads();
        gemm_block(Bsh + (kb & 1) * 4096);
        __syncthreads();
    }

    // ---- epilogue 1: m = fp16(silu(.+eb2)) -> g_M ----
    int r0 = wr * 32 + (lane >> 2);
    int e0 = ebase + r0;
    #pragma unroll
    for (int mf = 0; mf < 2; mf++) {
        int ea = e0 + mf * 16;
        #pragma unroll
        for (int nf = 0; nf < 8; nf++) {
            int col = cg * 64 + nf * 8 + (lane & 3) * 2;
            float m0 = silu_f(acc[mf][nf][0] + s_eb2[col]);
            float m1 = silu_f(acc[mf][nf][1] + s_eb2[col + 1]);
            float m2 = silu_f(acc[mf][nf][2] + s_eb2[col]);
            float m3 = silu_f(acc[mf][nf][3] + s_eb2[col + 1]);
            *(uint32_t*)(g_M + (size_t)ea * 128 + col)       = f2h2(m0, m1);
            *(uint32_t*)(g_M + (size_t)(ea + 8) * 128 + col) = f2h2(m2, m3);
            acc[mf][nf][0] = 0.f; acc[mf][nf][1] = 0.f;
            acc[mf][nf][2] = 0.f; acc[mf][nf][3] = 0.f;
        }
    }
    __syncthreads();

    // ---- GEMM 2: m @ cW1 ----
    ldA2(0);
    #pragma unroll
    for (int kb = 0; kb < 4; kb++) {
        stA();
        if (kb < 3) {
            cpBh(c1pk + (size_t)(kb + 1) * 4096, (kb + 1) & 1);
            ldA2(kb + 1);
            CP_WAIT1();
        } else {
            CP_WAIT0();
        }
        __syncthreads();
        gemm_block(Bsh + (kb & 1) * 4096);
        __syncthreads();
    }

    // ---- epilogue 2: gate + fused shift atomics ----
    float gp[4] = {0.f, 0.f, 0.f, 0.f};
    #pragma unroll
    for (int mf = 0; mf < 2; mf++) {
        #pragma unroll
        for (int nf = 0; nf < 8; nf++) {
            int col = cg * 64 + nf * 8 + (lane & 3) * 2;
            gp[mf * 2]     += silu_f(acc[mf][nf][0] + s_cb1[col]) * s_cw2[col]
                            + silu_f(acc[mf][nf][1] + s_cb1[col + 1]) * s_cw2[col + 1];
            gp[mf * 2 + 1] += silu_f(acc[mf][nf][2] + s_cb1[col]) * s_cw2[col]
                            + silu_f(acc[mf][nf][3] + s_cb1[col + 1]) * s_cw2[col + 1];
        }
    }
    #pragma unroll
    for (int j = 0; j < 4; j++) {
        gp[j] += __shfl_xor_sync(0xffffffffu, gp[j], 1);
        gp[j] += __shfl_xor_sync(0xffffffffu, gp[j], 2);
    }
    if ((lane & 3) == 0) {
        int rl = wr * 32 + (lane >> 2);
        s_gate[rl * 2 + cg]        = gp[0];
        s_gate[(rl + 8) * 2 + cg]  = gp[1];
        s_gate[(rl + 16) * 2 + cg] = gp[2];
        s_gate[(rl + 24) * 2 + cg] = gp[3];
    }
    __syncthreads();
    if (tid < 128) {
        float gt = s_gate[tid * 2] + s_gate[tid * 2 + 1];
        int s = s_src[tid], d = s_dst[tid];
        float dx = coords[s * 3 + 0] - coords[d * 3 + 0];
        float dy = coords[s * 3 + 1] - coords[d * 3 + 1];
        float dz = coords[s * 3 + 2] - coords[d * 3 + 2];
        float q = gt * __frsqrt_rn(s_ds[tid] + 1e-8f);
        atomicAdd(&g_shift[d * 3 + 0], dx * q);
        atomicAdd(&g_shift[d * 3 + 1], dy * q);
        atomicAdd(&g_shift[d * 3 + 2], dz * q);
    }
}

__global__ void finalize_kernel(float* __restrict__ out) {
    int n = blockIdx.x, tid = threadIdx.x;
    out[NN * 3 + n * 128 + tid] = g_h[n * 128 + tid];
    if (tid < 3) out[n * 3 + tid] = g_shift[n * 3 + tid];
}

// ================= host =================
extern "C" void kernel_launch(void* const* d_in, const int* in_sizes, int n_in,
                              void* d_out, int out_size) {
    const float* z      = (const float*)d_in[0];
    const float* t      = (const float*)d_in[1];
    const float* coords = (const float*)d_in[2];
    const int*   species= (const int*)d_in[3];
    const int*   batch  = (const int*)d_in[4];
    const int*   esrc   = (const int*)d_in[5];
    const int*   edst   = (const int*)d_in[6];
    const float* spemb  = (const float*)d_in[7];
    const float* tmW1   = (const float*)d_in[8];
    const float* tmb1   = (const float*)d_in[9];
    const float* tmW2   = (const float*)d_in[10];
    const float* tmb2   = (const float*)d_in[11];
    const float* neW    = (const float*)d_in[12];
    const float* neb    = (const float*)d_in[13];
    const float* eW1    = (const float*)d_in[14];
    const float* eb1    = (const float*)d_in[15];
    const float* eW2    = (const float*)d_in[16];
    const float* eb2    = (const float*)d_in[17];
    const float* cW1    = (const float*)d_in[18];
    const float* cb1    = (const float*)d_in[19];
    const float* cW2    = (const float*)d_in[20];
    const float* nW1    = (const float*)d_in[21];
    const float* nb1    = (const float*)d_in[22];
    const float* nW2    = (const float*)d_in[23];
    const float* nb2    = (const float*)d_in[24];

    float *pX, *pP, *pU, *pH, *pBiasP;
    __half *pM, *pPkh;
    cudaGetSymbolAddress((void**)&pX,    g_X);
    cudaGetSymbolAddress((void**)&pP,    g_P);
    cudaGetSymbolAddress((void**)&pU,    g_u);
    cudaGetSymbolAddress((void**)&pH,    g_h);
    cudaGetSymbolAddress((void**)&pM,    g_M);
    cudaGetSymbolAddress((void**)&pPkh,  g_packWh);
    cudaGetSymbolAddress((void**)&pBiasP, g_biasP);

    cudaFuncSetAttribute(mma_edge, cudaFuncAttributeMaxDynamicSharedMemorySize, EDGE_SMEM);
    cudaFuncSetAttribute(mma_node<1,1,false,false,true>,  cudaFuncAttributeMaxDynamicSharedMemorySize, NODE_SMEM1);
    cudaFuncSetAttribute(mma_node<2,0,false,false,false>, cudaFuncAttributeMaxDynamicSharedMemorySize, NODE_SMEM2);
    cudaFuncSetAttribute(mma_node<1,2,true,false,false>,  cudaFuncAttributeMaxDynamicSharedMemorySize, NODE_SMEM1);
    cudaFuncSetAttribute(mma_node<1,0,false,true,true>,   cudaFuncAttributeMaxDynamicSharedMemorySize, NODE_SMEM1);

    const int MT = (NN + 127) / 128;   // 157

    setup_kernel<<<dim3(1024, 7), 256>>>(eW2, cW1, nW2, nW1, neW, eW1, eb1,
                                         t, tmW1, tmb1, tmW2, tmb2);
    // h0 = [z|sp] @ neW + neb
    mma_node<1, 1, false, false, true><<<MT, 256, NODE_SMEM1>>>(
        z, spemb, nullptr, species, batch, 128,
        pPkh + HK_NE, nullptr, neb, pH, 128, pX, 256, NN, 5, nullptr);

    for (int l = 0; l < NL; l++) {
        // P = [h|t] @ Wp
        mma_node<2, 0, false, false, false><<<MT, 256, NODE_SMEM2>>>(
            pX, nullptr, nullptr, nullptr, nullptr, 256,
            pPkh + HK_WP + (l * 2 + 0) * 32768, pPkh + HK_WP + (l * 2 + 1) * 32768,
            pBiasP + l * 256, pP, 256, nullptr, 0, NN, 8, nullptr);
        // fused edge: m + gate + shift
        mma_edge<<<NE / 128, 256, EDGE_SMEM>>>(
            esrc, edst, coords, pP,
            eW1 + (size_t)l * 385 * 128 + 256 * 128, eb2 + l * 128,
            pPkh + HK_EW2 + (size_t)l * 16384, pPkh + HK_CW1 + (size_t)l * 16384,
            cb1 + l * 128, cW2 + l * 128);
        // u = silu([h | sum12 m | t] @ nW1 + nb1)
        mma_node<1, 2, true, false, false><<<MT, 256, NODE_SMEM1>>>(
            pH, pM, pX + 128, nullptr, nullptr, 0,
            pPkh + HK_NW1 + l * 49152, nullptr, nb1 + l * 128,
            pU, 128, nullptr, 0, NN, 12, nullptr);
        // h = h + u @ nW2 + nb2
        mma_node<1, 0, false, true, true><<<MT, 256, NODE_SMEM1>>>(
            pU, nullptr, nullptr, nullptr, nullptr, 128,
            pPkh + HK_NW2 + l * 16384, nullptr, nb2 + l * 128,
            pH, 128, pX, 256, NN, 4, pH);
    }

    finalize_kernel<<<NN, 128>>>((float*)d_out);
}

// round 14
// speedup vs baseline: 1.0630x; 1.0630x over previous
#include <cuda_runtime.h>
#include <cuda_fp16.h>
#include <math.h>
#include <stdint.h>

#define NN 20000
#define NG 400
#define KNB 12
#define NE 240000
#define NL 4

// ---- packed tf32 weight region offsets (floats) ----
#define PK_NW2 131072
#define PK_NW1 196608
#define PK_NE  393216
#define PK_WP  413696
#define PK_TOTAL 675840

// ---- static device scratch ----
__device__ float g_temb[NG * 128];
__device__ float g_h[NN * 128];
__device__ float g_X[NN * 256];      // [h | t]
__device__ __half g_P[NN * 256];     // fp16 P
__device__ __half g_M[NE * 128];     // fp16 messages
__device__ float g_u[NN * 128];
__device__ float g_packW[PK_TOTAL];          // tf32 fragment images (node)
__device__ __half g_packWh[2 * NL * 16384];  // fp16 fragment images: [eW2 | cW1]
__device__ float g_biasP[NL * 256];
__device__ float g_shift[NN * 3];

__device__ __forceinline__ float silu_f(float x) {
    return __fdividef(x, 1.0f + __expf(-x));
}
__device__ __forceinline__ float to_tf32(float x) {
    float r; asm("cvt.rna.tf32.f32 %0, %1;" : "=f"(r) : "f"(x)); return r;
}
__device__ __forceinline__ uint32_t f2h2(float a, float b) {
    __half2 h = __floats2half2_rn(a, b);
    return *(uint32_t*)&h;
}

__device__ __forceinline__ void mma_tf32(float c[4], uint32_t a0, uint32_t a1,
                                         uint32_t a2, uint32_t a3,
                                         uint32_t b0, uint32_t b1) {
    asm volatile(
        "mma.sync.aligned.m16n8k8.row.col.f32.tf32.tf32.f32 "
        "{%0,%1,%2,%3}, {%4,%5,%6,%7}, {%8,%9}, {%0,%1,%2,%3};"
        : "+f"(c[0]), "+f"(c[1]), "+f"(c[2]), "+f"(c[3])
        : "r"(a0), "r"(a1), "r"(a2), "r"(a3), "r"(b0), "r"(b1));
}
__device__ __forceinline__ void mma_f16(float c[4], uint32_t a0, uint32_t a1,
                                        uint32_t a2, uint32_t a3,
                                        uint32_t b0, uint32_t b1) {
    asm volatile(
        "mma.sync.aligned.m16n8k16.row.col.f32.f16.f16.f32 "
        "{%0,%1,%2,%3}, {%4,%5,%6,%7}, {%8,%9}, {%0,%1,%2,%3};"
        : "+f"(c[0]), "+f"(c[1]), "+f"(c[2]), "+f"(c[3])
        : "r"(a0), "r"(a1), "r"(a2), "r"(a3), "r"(b0), "r"(b1));
}

__device__ __forceinline__ void cp16(uint32_t saddr, const void* g) {
    asm volatile("cp.async.ca.shared.global [%0], [%1], 16;" :: "r"(saddr), "l"(g));
}
#define CP_COMMIT() asm volatile("cp.async.commit_group;" ::: "memory")
#define CP_WAIT1()  asm volatile("cp.async.wait_group 1;" ::: "memory")
#define CP_WAIT0()  asm volatile("cp.async.wait_group 0;" ::: "memory")

// tf32 B layout per 32-K block (4096 fl): pos=(nf*2+(ks>>1))*128+lane*4+(ks&1)*2+pair
// fp16 B layout per 32-K block (4096 h): pos=(nf*32+lane)*8+q ;
//   k = kb*32 + (q>>1)*8 + (lane&3)*2 + (q&1) ; n = nf*8 + (lane>>2)

// ================= launch 0: setup = pack + temb =================
__global__ void setup_kernel(const float* __restrict__ eW2, const float* __restrict__ cW1,
                             const float* __restrict__ nW2, const float* __restrict__ nW1,
                             const float* __restrict__ neW, const float* __restrict__ eW1,
                             const float* __restrict__ eb1,
                             const float* __restrict__ t,
                             const float* __restrict__ tmW1, const float* __restrict__ tmb1,
                             const float* __restrict__ tmW2, const float* __restrict__ tmb2) {
    int f = blockIdx.y;
    int tid = threadIdx.x;

    if (f == 6) {                       // ---- time-embedding MLP ----
        int g = blockIdx.x;
        if (g >= NG) return;
        __shared__ float e[128];
        __shared__ float hid[256];
        float tv = t[g];
        if (tid < 64) {
            float fr = expf(-(float)tid * (logf(10000.0f) / 63.0f));
            float a = tv * fr;
            e[tid] = sinf(a); e[tid + 64] = cosf(a);
        }
        __syncthreads();
        {
            float s = tmb1[tid];
            #pragma unroll 4
            for (int k = 0; k < 128; k++) s = fmaf(e[k], tmW1[k * 256 + tid], s);
            hid[tid] = silu_f(s);
        }
        __syncthreads();
        if (tid < 128) {
            float s = tmb2[tid];
            #pragma unroll 4
            for (int k = 0; k < 256; k++) s = fmaf(hid[k], tmW2[k * 128 + tid], s);
            g_temb[g * 128 + tid] = s;
        }
        return;
    }

    int i = blockIdx.x * 256 + tid;

    if (f == 0) {                       // ---- fp16 pack: eW2 + cW1 ----
        if (i >= 2 * NL * 16384) return;
        int mat = i >> 16;
        int r16 = i & 65535;
        int l = r16 >> 14, r14 = r16 & 16383;
        int kb = r14 >> 12, rr = r14 & 4095;
        int q = rr & 7, lane = (rr >> 3) & 31, nf = rr >> 8;
        int k = kb * 32 + (q >> 1) * 8 + (lane & 3) * 2 + (q & 1);
        int n = nf * 8 + (lane >> 2);
        const float* W = (mat == 0 ? eW2 : cW1) + (size_t)l * 16384;
        g_packWh[(size_t)mat * NL * 16384 + r16] = __float2half(W[(size_t)k * 128 + n]);
        return;
    }

    int kb, rr, dstbase;
    const float* src = nullptr;
    if (f == 1) {                       // nW2 tf32
        if (i >= 65536) return;
        int l = i >> 14, r14 = i & 16383;
        kb = r14 >> 12; rr = r14 & 4095;
        src = nW2 + (size_t)l * 16384;
        dstbase = PK_NW2 + l * 16384;
    } else if (f == 2) {
        return;
    } else if (f == 3) {
        if (i >= 196608) return;
        int l = i / 49152, r = i % 49152;
        kb = r >> 12; rr = r & 4095;
        src = nW1 + (size_t)l * 49152;
        dstbase = PK_NW1 + l * 49152;
    } else if (f == 4) {
        if (i >= 20480) {
            if (i < 21504) {
                int idx2 = i - 20480;
                int l = idx2 >> 8, c = idx2 & 255;
                g_biasP[l * 256 + c] = (c < 128) ? eb1[l * 128 + c] : 0.f;
            }
            return;
        }
        kb = i >> 12; rr = i & 4095;
        src = neW;
        dstbase = PK_NE;
    } else {                            // f == 5: folded eW1 -> Wp (tf32)
        if (i >= 262144) return;
        int l = i >> 16, r = i & 65535, slab = r >> 15, r2 = r & 32767;
        kb = r2 >> 12; rr = r2 & 4095;
        int hi = rr >> 7, lo = rr & 127;
        int nf = hi >> 1, ksh = hi & 1;
        int lane = lo >> 2, tb = lo & 3;
        int ks = ksh * 2 + (tb >> 1), pair = tb & 1;
        int k = kb * 32 + ks * 8 + (lane & 3) + pair * 4;
        int n = nf * 8 + (lane >> 2);
        const float* W = eW1 + (size_t)l * 385 * 128;
        float v;
        if (slab == 0) v = (k < 128) ? W[k * 128 + n] : W[(257 + (k - 128)) * 128 + n];
        else           v = (k < 128) ? W[(128 + k) * 128 + n] : 0.f;
        g_packW[PK_WP + (l * 2 + slab) * 32768 + kb * 4096 + rr] = to_tf32(v);
        return;
    }
    int hi = rr >> 7, lo = rr & 127;
    int nf = hi >> 1, ksh = hi & 1;
    int lane = lo >> 2, tb = lo & 3;
    int ks = ksh * 2 + (tb >> 1), pair = tb & 1;
    int k = kb * 32 + ks * 8 + (lane & 3) + pair * 4;
    int n = nf * 8 + (lane >> 2);
    g_packW[dstbase + kb * 4096 + rr] = to_tf32(src[(size_t)k * 128 + n]);
}

// ================= pipelined node GEMM (tf32) =================
// MODE 0: plain; MODE 1: ne (+t-fill/shift-zero); MODE 2: MI ([h|sum12 m|t])
// HOUT: C is __half*; FINAL: prologue copies g_shift -> shift_out
template <int NS, int MODE, bool SILU, bool RES, bool DUAL, bool HOUT, bool FINAL>
__global__ void __launch_bounds__(256) mma_node(
    const float* __restrict__ A0, const void* __restrict__ A1v,
    const float* __restrict__ A2, const int* __restrict__ idxp,
    const int* __restrict__ batch, int ldA,
    const float* __restrict__ W0, const float* __restrict__ W1,
    const float* __restrict__ bias,
    void* __restrict__ Cv, int ldC, float* __restrict__ C2, int ldC2,
    int M, int Kb, const float* __restrict__ Rsrc,
    float* __restrict__ shift_out) {
    extern __shared__ float sm[];
    float* As = sm;
    float* Bs = sm + 4608;
    float* s_bias = Bs + 2 * 4096 * NS;
    int tid = threadIdx.x, w = tid >> 5, lane = tid & 31;
    for (int i = tid; i < NS * 128; i += 256) s_bias[i] = bias[i];
    int m0 = blockIdx.x * 128;
    uint32_t bs_sm = (uint32_t)__cvta_generic_to_shared(Bs);

    if (MODE == 1) {
        for (int idx = tid; idx < 4096; idx += 256) {
            int r = idx >> 5, c4 = idx & 31;
            int row = m0 + r;
            if (row < NN) {
                float4 tv = *(const float4*)(g_temb + (size_t)batch[row] * 128 + c4 * 4);
                *(float4*)(g_X + (size_t)row * 256 + 128 + c4 * 4) = tv;
            }
        }
        if (tid < 128) {
            int row = m0 + tid;
            if (row < NN) {
                g_shift[row * 3 + 0] = 0.f;
                g_shift[row * 3 + 1] = 0.f;
                g_shift[row * 3 + 2] = 0.f;
            }
        }
    }
    if (FINAL) {
        for (int idx = tid; idx < 384; idx += 256) {
            int g = m0 * 3 + idx;
            if (g < NN * 3) shift_out[g] = g_shift[g];
        }
    }

    float acc[NS][16][4];
    #pragma unroll
    for (int s = 0; s < NS; s++)
        #pragma unroll
        for (int nf = 0; nf < 16; nf++)
            #pragma unroll
            for (int j = 0; j < 4; j++) acc[s][nf][j] = 0.f;

    float4 av[4];
    auto ldA_regs = [&](int kb) {
        #pragma unroll
        for (int i = 0; i < 4; i++) {
            int idx = tid + i * 256;
            int r = idx >> 3, c4 = idx & 7;
            int row = m0 + r;
            float4 v = make_float4(0.f, 0.f, 0.f, 0.f);
            if (row < M) {
                if (MODE == 0) {
                    v = *(const float4*)(A0 + (size_t)row * ldA + kb * 32 + c4 * 4);
                } else if (MODE == 1) {
                    if (kb < 4) v = *(const float4*)(A0 + (size_t)row * 128 + kb * 32 + c4 * 4);
                    else        v = *(const float4*)((const float*)A1v + (size_t)idxp[row] * 32 + c4 * 4);
                } else {
                    if (kb < 4) {
                        v = *(const float4*)(A0 + (size_t)row * 128 + kb * 32 + c4 * 4);
                    } else if (kb < 8) {
                        const __half* Mh = (const __half*)A1v;
                        const __half* base = Mh + (size_t)row * KNB * 128 + (kb - 4) * 32 + c4 * 4;
                        #pragma unroll
                        for (int j = 0; j < KNB; j++) {
                            uint2 u = *(const uint2*)(base + (size_t)j * 128);
                            __half2 h0 = *(__half2*)&u.x;
                            __half2 h1 = *(__half2*)&u.y;
                            float2 f0 = __half22float2(h0);
                            float2 f1 = __half22float2(h1);
                            v.x += f0.x; v.y += f0.y; v.z += f1.x; v.w += f1.y;
                        }
                    } else {
                        v = *(const float4*)(A2 + (size_t)row * 256 + (kb - 8) * 32 + c4 * 4);
                    }
                }
            }
            av[i] = v;
        }
    };
    auto stA = [&]() {
        #pragma unroll
        for (int i = 0; i < 4; i++) {
            int idx = tid + i * 256;
            int r = idx >> 3, c4 = idx & 7;
            float4 v;
            v.x = to_tf32(av[i].x); v.y = to_tf32(av[i].y);
            v.z = to_tf32(av[i].z); v.w = to_tf32(av[i].w);
            *(float4*)(As + r * 36 + c4 * 4) = v;
        }
    };
    auto cpB = [&](int kb, int buf) {
        uint32_t dst = bs_sm + buf * (4096 * NS) * 4;
        const float* s0 = W0 + (size_t)kb * 4096;
        #pragma unroll
        for (int j = 0; j < 4; j++)
            cp16(dst + (tid + j * 256) * 16, s0 + (tid + j * 256) * 4);
        if constexpr (NS == 2) {
            const float* s1 = W1 + (size_t)kb * 4096;
            #pragma unroll
            for (int j = 0; j < 4; j++)
                cp16(dst + 16384 + (tid + j * 256) * 16, s1 + (tid + j * 256) * 4);
        }
        CP_COMMIT();
    };

    ldA_regs(0);
    cpB(0, 0);
    for (int kb = 0; kb < Kb; kb++) {
        int cur = kb & 1;
        stA();
        if (kb + 1 < Kb) {
            cpB(kb + 1, cur ^ 1);
            ldA_regs(kb + 1);
            CP_WAIT1();
        } else {
            CP_WAIT0();
        }
        __syncthreads();
        const float* Bb = Bs + cur * (4096 * NS);
        #pragma unroll
        for (int ksh = 0; ksh < 2; ksh++) {
            const float* ap = As + (w * 16 + (lane >> 2)) * 36 + ksh * 16 + (lane & 3);
            uint32_t p00 = __float_as_uint(ap[0]);
            uint32_t p01 = __float_as_uint(ap[8 * 36]);
            uint32_t p02 = __float_as_uint(ap[4]);
            uint32_t p03 = __float_as_uint(ap[8 * 36 + 4]);
            uint32_t p10 = __float_as_uint(ap[8]);
            uint32_t p11 = __float_as_uint(ap[8 * 36 + 8]);
            uint32_t p12 = __float_as_uint(ap[12]);
            uint32_t p13 = __float_as_uint(ap[8 * 36 + 12]);
            #pragma unroll
            for (int nf = 0; nf < 16; nf++) {
                float4 b = *(const float4*)(Bb + (nf * 2 + ksh) * 128 + lane * 4);
                mma_tf32(acc[0][nf], p00, p01, p02, p03,
                         __float_as_uint(b.x), __float_as_uint(b.y));
                mma_tf32(acc[0][nf], p10, p11, p12, p13,
                         __float_as_uint(b.z), __float_as_uint(b.w));
                if constexpr (NS == 2) {
                    float4 b1v = *(const float4*)(Bb + 4096 + (nf * 2 + ksh) * 128 + lane * 4);
                    mma_tf32(acc[1][nf], p00, p01, p02, p03,
                             __float_as_uint(b1v.x), __float_as_uint(b1v.y));
                    mma_tf32(acc[1][nf], p10, p11, p12, p13,
                             __float_as_uint(b1v.z), __float_as_uint(b1v.w));
                }
            }
        }
        __syncthreads();
    }

    int r0 = w * 16 + (lane >> 2);
    int row0 = m0 + r0, row1 = row0 + 8;
    #pragma unroll
    for (int s = 0; s < NS; s++) {
        #pragma unroll
        for (int nf = 0; nf < 16; nf++) {
            int lc = nf * 8 + (lane & 3) * 2;
            int col = s * 128 + lc;
            float v0 = acc[s][nf][0] + s_bias[col];
            float v1 = acc[s][nf][1] + s_bias[col + 1];
            float v2 = acc[s][nf][2] + s_bias[col];
            float v3 = acc[s][nf][3] + s_bias[col + 1];
            if (SILU) { v0 = silu_f(v0); v1 = silu_f(v1); v2 = silu_f(v2); v3 = silu_f(v3); }
            if constexpr (HOUT) {
                __half* Ch = (__half*)Cv;
                if (row0 < M)
                    *(uint32_t*)(Ch + (size_t)row0 * ldC + col) = f2h2(v0, v1);
                if (row1 < M)
                    *(uint32_t*)(Ch + (size_t)row1 * ldC + col) = f2h2(v2, v3);
            } else {
                float* C = (float*)Cv;
                if (row0 < M) {
                    if (RES) {
                        float2 r = *(const float2*)(Rsrc + (size_t)row0 * 128 + col);
                        v0 += r.x; v1 += r.y;
                    }
                    *(float2*)(C + (size_t)row0 * ldC + col) = make_float2(v0, v1);
                    if (DUAL) *(float2*)(C2 + (size_t)row0 * ldC2 + col) = make_float2(v0, v1);
                }
                if (row1 < M) {
                    if (RES) {
                        float2 r = *(const float2*)(Rsrc + (size_t)row1 * 128 + col);
                        v2 += r.x; v3 += r.y;
                    }
                    *(float2*)(C + (size_t)row1 * ldC + col) = make_float2(v2, v3);
                    if (DUAL) *(float2*)(C2 + (size_t)row1 * ldC2 + col) = make_float2(v2, v3);
                }
            }
        }
    }
}
#define NODE_SMEM1 51712
#define NODE_SMEM2 84992

// ================= fused edge kernel (fp16 m16n8k16, fp16 P) =================
#define EDGE_SMEM 31232
__global__ void __launch_bounds__(256, 2) mma_edge(
    const int* __restrict__ esrc, const int* __restrict__ edst,
    const float* __restrict__ coords, const __half* __restrict__ P,
    const float* __restrict__ wc, const float* __restrict__ eb2,
    const __half* __restrict__ w2pk, const __half* __restrict__ c1pk,
    const float* __restrict__ cb1, const float* __restrict__ cw2) {
    extern __shared__ char smc[];
    __half* Ah    = (__half*)smc;                 // 128 x 40 halves
    __half* Bsh   = (__half*)(smc + 10240);       // 2 x 4096 halves
    float* s_gate = (float*)(smc + 26624);        // 256
    int* s_src    = (int*)(smc + 27648);
    int* s_dst    = (int*)(smc + 28160);
    float* s_ds   = (float*)(smc + 28672);
    float* s_wc   = (float*)(smc + 29184);
    float* s_eb2  = (float*)(smc + 29696);
    float* s_cb1  = (float*)(smc + 30208);
    float* s_cw2  = (float*)(smc + 30720);
    int tid = threadIdx.x, w = tid >> 5, lane = tid & 31;
    int wr = w & 3, cg = w >> 2;
    uint32_t bsh_sm = (uint32_t)__cvta_generic_to_shared(Bsh);
    int ebase = blockIdx.x * 128;

    auto cpBh = [&](const __half* src, int buf) {
        uint32_t dst = bsh_sm + buf * 8192;
        #pragma unroll
        for (int j = 0; j < 2; j++)
            cp16(dst + (tid + j * 256) * 16, src + (tid + j * 256) * 8);
        CP_COMMIT();
    };

    cpBh(w2pk, 0);

    if (tid < 128) {
        int e = ebase + tid;
        int s = esrc[e], d = edst[e];
        s_src[tid] = s; s_dst[tid] = d;
        float dx = coords[s * 3 + 0] - coords[d * 3 + 0];
        float dy = coords[s * 3 + 1] - coords[d * 3 + 1];
        float dz = coords[s * 3 + 2] - coords[d * 3 + 2];
        s_ds[tid] = dx * dx + dy * dy + dz * dz;
        s_wc[tid] = wc[tid];
        s_eb2[tid] = eb2[tid];
        s_cb1[tid] = cb1[tid];
        s_cw2[tid] = cw2[tid];
    }
    __syncthreads();

    uint4 av[2];
    auto ldA1 = [&](int kb) {   // build A slice kb from fp16 P (LDG + silu -> fp16 regs)
        #pragma unroll
        for (int i = 0; i < 2; i++) {
            int idx = tid + i * 256;
            int r = idx >> 2, c8 = idx & 3;
            int s = s_src[r], d = s_dst[r];
            float ds = s_ds[r];
            uint4 us = *(const uint4*)(P + (size_t)s * 256 + kb * 32 + c8 * 8);
            uint4 ud = *(const uint4*)(P + (size_t)d * 256 + 128 + kb * 32 + c8 * 8);
            const float* Wv = s_wc + kb * 32 + c8 * 8;
            float4 w0 = *(const float4*)Wv, w1 = *(const float4*)(Wv + 4);
            float2 s0 = __half22float2(*(__half2*)&us.x);
            float2 s1 = __half22float2(*(__half2*)&us.y);
            float2 s2 = __half22float2(*(__half2*)&us.z);
            float2 s3 = __half22float2(*(__half2*)&us.w);
            float2 d0 = __half22float2(*(__half2*)&ud.x);
            float2 d1 = __half22float2(*(__half2*)&ud.y);
            float2 d2 = __half22float2(*(__half2*)&ud.z);
            float2 d3 = __half22float2(*(__half2*)&ud.w);
            float v0 = silu_f(s0.x + d0.x + ds * w0.x);
            float v1 = silu_f(s0.y + d0.y + ds * w0.y);
            float v2 = silu_f(s1.x + d1.x + ds * w0.z);
            float v3 = silu_f(s1.y + d1.y + ds * w0.w);
            float v4 = silu_f(s2.x + d2.x + ds * w1.x);
            float v5 = silu_f(s2.y + d2.y + ds * w1.y);
            float v6 = silu_f(s3.x + d3.x + ds * w1.z);
            float v7 = silu_f(s3.y + d3.y + ds * w1.w);
            av[i].x = f2h2(v0, v1); av[i].y = f2h2(v2, v3);
            av[i].z = f2h2(v4, v5); av[i].w = f2h2(v6, v7);
        }
    };
    auto ldA2 = [&](int kb) {
        #pragma unroll
        for (int i = 0; i < 2; i++) {
            int idx = tid + i * 256;
            int r = idx >> 2, c8 = idx & 3;
            av[i] = *(const uint4*)(g_M + (size_t)(ebase + r) * 128 + kb * 32 + c8 * 8);
        }
    };
    auto stA = [&]() {
        #pragma unroll
        for (int i = 0; i < 2; i++) {
            int idx = tid + i * 256;
            int r = idx >> 2, c8 = idx & 3;
            *(uint4*)(Ah + r * 40 + c8 * 8) = av[i];
        }
    };

    float acc[2][8][4];
    #pragma unroll
    for (int mf = 0; mf < 2; mf++)
        #pragma unroll
        for (int nf = 0; nf < 8; nf++)
            #pragma unroll
            for (int j = 0; j < 4; j++) acc[mf][nf][j] = 0.f;

    auto gemm_block = [&](const __half* Bb) {
        uint32_t Areg[2][2][4];
        const __half* ap = Ah + (wr * 32 + (lane >> 2)) * 40 + (lane & 3) * 2;
        #pragma unroll
        for (int mf = 0; mf < 2; mf++) {
            const __half* base = ap + mf * 16 * 40;
            #pragma unroll
            for (int ks = 0; ks < 2; ks++) {
                const __half* p = base + ks * 16;
                Areg[mf][ks][0] = *(const uint32_t*)(p);
                Areg[mf][ks][1] = *(const uint32_t*)(p + 8 * 40);
                Areg[mf][ks][2] = *(const uint32_t*)(p + 8);
                Areg[mf][ks][3] = *(const uint32_t*)(p + 8 * 40 + 8);
            }
        }
        #pragma unroll
        for (int nf = 0; nf < 8; nf++) {
            uint4 bv = *(const uint4*)(Bb + ((cg * 8 + nf) * 32 + lane) * 8);
            #pragma unroll
            for (int mf = 0; mf < 2; mf++) {
                mma_f16(acc[mf][nf], Areg[mf][0][0], Areg[mf][0][1], Areg[mf][0][2], Areg[mf][0][3],
                        bv.x, bv.y);
                mma_f16(acc[mf][nf], Areg[mf][1][0], Areg[mf][1][1], Areg[mf][1][2], Areg[mf][1][3],
                        bv.z, bv.w);
            }
        }
    };

    // ---- GEMM 1: pre @ eW2 ----
    ldA1(0);
    #pragma unroll
    for (int kb = 0; kb < 4; kb++) {
        stA();
        if (kb < 3) {
            cpBh(w2pk + (size_t)(kb + 1) * 4096, (kb + 1) & 1);
            ldA1(kb + 1);
        } else {
            cpBh(c1pk, 0);
        }
        CP_WAIT1();
        __syncthreads();
        gemm_block(Bsh + (kb & 1) * 4096);
        __syncthreads();
    }

    // ---- epilogue 1: m = fp16(silu(.+eb2)) -> g_M ----
    int r0 = wr * 32 + (lane >> 2);
    int e0 = ebase + r0;
    #pragma unroll
    for (int mf = 0; mf < 2; mf++) {
        int ea = e0 + mf * 16;
        #pragma unroll
        for (int nf = 0; nf < 8; nf++) {
            int col = cg * 64 + nf * 8 + (lane & 3) * 2;
            float m0 = silu_f(acc[mf][nf][0] + s_eb2[col]);
            float m1 = silu_f(acc[mf][nf][1] + s_eb2[col + 1]);
            float m2 = silu_f(acc[mf][nf][2] + s_eb2[col]);
            float m3 = silu_f(acc[mf][nf][3] + s_eb2[col + 1]);
            *(uint32_t*)(g_M + (size_t)ea * 128 + col)       = f2h2(m0, m1);
            *(uint32_t*)(g_M + (size_t)(ea + 8) * 128 + col) = f2h2(m2, m3);
            acc[mf][nf][0] = 0.f; acc[mf][nf][1] = 0.f;
            acc[mf][nf][2] = 0.f; acc[mf][nf][3] = 0.f;
        }
    }
    __syncthreads();

    // ---- GEMM 2: m @ cW1 ----
    ldA2(0);
    #pragma unroll
    for (int kb = 0; kb < 4; kb++) {
        stA();
        if (kb < 3) {
            cpBh(c1pk + (size_t)(kb + 1) * 4096, (kb + 1) & 1);
            ldA2(kb + 1);
            CP_WAIT1();
        } else {
            CP_WAIT0();
        }
        __syncthreads();
        gemm_block(Bsh + (kb & 1) * 4096);
        __syncthreads();
    }

    // ---- epilogue 2: gate + fused shift atomics ----
    float gp[4] = {0.f, 0.f, 0.f, 0.f};
    #pragma unroll
    for (int mf = 0; mf < 2; mf++) {
        #pragma unroll
        for (int nf = 0; nf < 8; nf++) {
            int col = cg * 64 + nf * 8 + (lane & 3) * 2;
            gp[mf * 2]     += silu_f(acc[mf][nf][0] + s_cb1[col]) * s_cw2[col]
                            + silu_f(acc[mf][nf][1] + s_cb1[col + 1]) * s_cw2[col + 1];
            gp[mf * 2 + 1] += silu_f(acc[mf][nf][2] + s_cb1[col]) * s_cw2[col]
                            + silu_f(acc[mf][nf][3] + s_cb1[col + 1]) * s_cw2[col + 1];
        }
    }
    #pragma unroll
    for (int j = 0; j < 4; j++) {
        gp[j] += __shfl_xor_sync(0xffffffffu, gp[j], 1);
        gp[j] += __shfl_xor_sync(0xffffffffu, gp[j], 2);
    }
    if ((lane & 3) == 0) {
        int rl = wr * 32 + (lane >> 2);
        s_gate[rl * 2 + cg]        = gp[0];
        s_gate[(rl + 8) * 2 + cg]  = gp[1];
        s_gate[(rl + 16) * 2 + cg] = gp[2];
        s_gate[(rl + 24) * 2 + cg] = gp[3];
    }
    __syncthreads();
    if (tid < 128) {
        float gt = s_gate[tid * 2] + s_gate[tid * 2 + 1];
        int s = s_src[tid], d = s_dst[tid];
        float dx = coords[s * 3 + 0] - coords[d * 3 + 0];
        float dy = coords[s * 3 + 1] - coords[d * 3 + 1];
        float dz = coords[s * 3 + 2] - coords[d * 3 + 2];
        float q = gt * __frsqrt_rn(s_ds[tid] + 1e-8f);
        atomicAdd(&g_shift[d * 3 + 0], dx * q);
        atomicAdd(&g_shift[d * 3 + 1], dy * q);
        atomicAdd(&g_shift[d * 3 + 2], dz * q);
    }
}

// ================= host =================
extern "C" void kernel_launch(void* const* d_in, const int* in_sizes, int n_in,
                              void* d_out, int out_size) {
    const float* z      = (const float*)d_in[0];
    const float* t      = (const float*)d_in[1];
    const float* coords = (const float*)d_in[2];
    const int*   species= (const int*)d_in[3];
    const int*   batch  = (const int*)d_in[4];
    const int*   esrc   = (const int*)d_in[5];
    const int*   edst   = (const int*)d_in[6];
    const float* spemb  = (const float*)d_in[7];
    const float* tmW1   = (const float*)d_in[8];
    const float* tmb1   = (const float*)d_in[9];
    const float* tmW2   = (const float*)d_in[10];
    const float* tmb2   = (const float*)d_in[11];
    const float* neW    = (const float*)d_in[12];
    const float* neb    = (const float*)d_in[13];
    const float* eW1    = (const float*)d_in[14];
    const float* eb1    = (const float*)d_in[15];
    const float* eW2    = (const float*)d_in[16];
    const float* eb2    = (const float*)d_in[17];
    const float* cW1    = (const float*)d_in[18];
    const float* cb1    = (const float*)d_in[19];
    const float* cW2    = (const float*)d_in[20];
    const float* nW1    = (const float*)d_in[21];
    const float* nb1    = (const float*)d_in[22];
    const float* nW2    = (const float*)d_in[23];
    const float* nb2    = (const float*)d_in[24];
    float* out = (float*)d_out;

    float *pX, *pU, *pH, *pPk, *pBiasP;
    __half *pM, *pP, *pPkh;
    cudaGetSymbolAddress((void**)&pX,    g_X);
    cudaGetSymbolAddress((void**)&pP,    g_P);
    cudaGetSymbolAddress((void**)&pU,    g_u);
    cudaGetSymbolAddress((void**)&pH,    g_h);
    cudaGetSymbolAddress((void**)&pM,    g_M);
    cudaGetSymbolAddress((void**)&pPk,   g_packW);
    cudaGetSymbolAddress((void**)&pPkh,  g_packWh);
    cudaGetSymbolAddress((void**)&pBiasP, g_biasP);

    cudaFuncSetAttribute(mma_edge, cudaFuncAttributeMaxDynamicSharedMemorySize, EDGE_SMEM);
    cudaFuncSetAttribute(mma_node<1,1,false,false,true,false,false>,  cudaFuncAttributeMaxDynamicSharedMemorySize, NODE_SMEM1);
    cudaFuncSetAttribute(mma_node<2,0,false,false,false,true,false>,  cudaFuncAttributeMaxDynamicSharedMemorySize, NODE_SMEM2);
    cudaFuncSetAttribute(mma_node<1,2,true,false,false,false,false>,  cudaFuncAttributeMaxDynamicSharedMemorySize, NODE_SMEM1);
    cudaFuncSetAttribute(mma_node<1,0,false,true,true,false,false>,   cudaFuncAttributeMaxDynamicSharedMemorySize, NODE_SMEM1);
    cudaFuncSetAttribute(mma_node<1,0,false,true,false,false,true>,   cudaFuncAttributeMaxDynamicSharedMemorySize, NODE_SMEM1);

    const int MT = (NN + 127) / 128;   // 157

    setup_kernel<<<dim3(1024, 7), 256>>>(eW2, cW1, nW2, nW1, neW, eW1, eb1,
                                         t, tmW1, tmb1, tmW2, tmb2);
    // h0 = [z|sp] @ neW + neb  (dual-store h, X[:, :128])
    mma_node<1, 1, false, false, true, false, false><<<MT, 256, NODE_SMEM1>>>(
        z, spemb, nullptr, species, batch, 128,
        pPk + PK_NE, nullptr, neb, pH, 128, pX, 256, NN, 5, nullptr, nullptr);

    for (int l = 0; l < NL; l++) {
        // P = [h|t] @ Wp  -> fp16 g_P
        mma_node<2, 0, false, false, false, true, false><<<MT, 256, NODE_SMEM2>>>(
            pX, nullptr, nullptr, nullptr, nullptr, 256,
            pPk + PK_WP + (l * 2 + 0) * 32768, pPk + PK_WP + (l * 2 + 1) * 32768,
            pBiasP + l * 256, pP, 256, nullptr, 0, NN, 8, nullptr, nullptr);
        // fused edge: m + gate + shift
        mma_edge<<<NE / 128, 256, EDGE_SMEM>>>(
            esrc, edst, coords, pP,
            eW1 + (size_t)l * 385 * 128 + 256 * 128, eb2 + l * 128,
            pPkh + (size_t)l * 16384, pPkh + (size_t)(NL + l) * 16384,
            cb1 + l * 128, cW2 + l * 128);
        // u = silu([h | sum12 m | t] @ nW1 + nb1)
        mma_node<1, 2, true, false, false, false, false><<<MT, 256, NODE_SMEM1>>>(
            pH, pM, pX + 128, nullptr, nullptr, 0,
            pPk + PK_NW1 + l * 49152, nullptr, nb1 + l * 128,
            pU, 128, nullptr, 0, NN, 12, nullptr, nullptr);
        if (l < NL - 1) {
            // h = h + u @ nW2 + nb2  (dual-store h, X)
            mma_node<1, 0, false, true, true, false, false><<<MT, 256, NODE_SMEM1>>>(
                pU, nullptr, nullptr, nullptr, nullptr, 128,
                pPk + PK_NW2 + l * 16384, nullptr, nb2 + l * 128,
                pH, 128, pX, 256, NN, 4, pH, nullptr);
        } else {
            // final: h -> out[NN*3 + ...], shift -> out[0:NN*3]
            mma_node<1, 0, false, true, false, false, true><<<MT, 256, NODE_SMEM1>>>(
                pU, nullptr, nullptr, nullptr, nullptr, 128,
                pPk + PK_NW2 + l * 16384, nullptr, nb2 + l * 128,
                out + NN * 3, 128, nullptr, 0, NN, 4, pH, out);
        }
    }
}

// round 15
// speedup vs baseline: 1.0750x; 1.0113x over previous
#include <cuda_runtime.h>
#include <cuda_fp16.h>
#include <math.h>
#include <stdint.h>

#define NN 20000
#define NG 400
#define KNB 12
#define NE 240000
#define NL 4

// ---- packed tf32 weight region offsets (floats) ----
#define PK_NW2 131072
#define PK_NW1 196608
#define PK_NE  393216
#define PK_WP  413696
#define PK_TOTAL 675840

// ---- static device scratch ----
__device__ float g_temb[NG * 128];
__device__ float g_h[NN * 128];
__device__ float g_X[NN * 256];      // [h | t]
__device__ __half g_P[NN * 256];     // fp16 P
__device__ __half g_M[NE * 128];     // fp16 messages
__device__ float g_u[NN * 128];
__device__ float g_packW[PK_TOTAL];          // tf32 fragment images (node)
__device__ __half g_packWh[2 * NL * 16384];  // fp16 fragment images: [eW2 | cW1]
__device__ float g_biasP[NL * 256];
__device__ float g_shift[NN * 3];

__device__ __forceinline__ float silu_f(float x) {
    return __fdividef(x, 1.0f + __expf(-x));
}
__device__ __forceinline__ float to_tf32(float x) {
    float r; asm("cvt.rna.tf32.f32 %0, %1;" : "=f"(r) : "f"(x)); return r;
}
__device__ __forceinline__ uint32_t f2h2(float a, float b) {
    __half2 h = __floats2half2_rn(a, b);
    return *(uint32_t*)&h;
}

__device__ __forceinline__ void mma_tf32(float c[4], uint32_t a0, uint32_t a1,
                                         uint32_t a2, uint32_t a3,
                                         uint32_t b0, uint32_t b1) {
    asm volatile(
        "mma.sync.aligned.m16n8k8.row.col.f32.tf32.tf32.f32 "
        "{%0,%1,%2,%3}, {%4,%5,%6,%7}, {%8,%9}, {%0,%1,%2,%3};"
        : "+f"(c[0]), "+f"(c[1]), "+f"(c[2]), "+f"(c[3])
        : "r"(a0), "r"(a1), "r"(a2), "r"(a3), "r"(b0), "r"(b1));
}
__device__ __forceinline__ void mma_f16(float c[4], uint32_t a0, uint32_t a1,
                                        uint32_t a2, uint32_t a3,
                                        uint32_t b0, uint32_t b1) {
    asm volatile(
        "mma.sync.aligned.m16n8k16.row.col.f32.f16.f16.f32 "
        "{%0,%1,%2,%3}, {%4,%5,%6,%7}, {%8,%9}, {%0,%1,%2,%3};"
        : "+f"(c[0]), "+f"(c[1]), "+f"(c[2]), "+f"(c[3])
        : "r"(a0), "r"(a1), "r"(a2), "r"(a3), "r"(b0), "r"(b1));
}

__device__ __forceinline__ void cp16(uint32_t saddr, const void* g) {
    asm volatile("cp.async.ca.shared.global [%0], [%1], 16;" :: "r"(saddr), "l"(g));
}
#define CP_COMMIT() asm volatile("cp.async.commit_group;" ::: "memory")
#define CP_WAIT1()  asm volatile("cp.async.wait_group 1;" ::: "memory")
#define CP_WAIT0()  asm volatile("cp.async.wait_group 0;" ::: "memory")

// tf32 B layout per 32-K block (4096 fl): pos=(nf*2+(ks>>1))*128+lane*4+(ks&1)*2+pair
// fp16 B layout per 32-K block (4096 h): pos=(nf*32+lane)*8+q ;
//   k = kb*32 + (q>>1)*8 + (lane&3)*2 + (q&1) ; n = nf*8 + (lane>>2)

// ================= launch 0: setup = pack + temb =================
__global__ void setup_kernel(const float* __restrict__ eW2, const float* __restrict__ cW1,
                             const float* __restrict__ nW2, const float* __restrict__ nW1,
                             const float* __restrict__ neW, const float* __restrict__ eW1,
                             const float* __restrict__ eb1,
                             const float* __restrict__ t,
                             const float* __restrict__ tmW1, const float* __restrict__ tmb1,
                             const float* __restrict__ tmW2, const float* __restrict__ tmb2) {
    int f = blockIdx.y;
    int tid = threadIdx.x;

    if (f == 6) {                       // ---- time-embedding MLP ----
        int g = blockIdx.x;
        if (g >= NG) return;
        __shared__ float e[128];
        __shared__ float hid[256];
        float tv = t[g];
        if (tid < 64) {
            float fr = expf(-(float)tid * (logf(10000.0f) / 63.0f));
            float a = tv * fr;
            e[tid] = sinf(a); e[tid + 64] = cosf(a);
        }
        __syncthreads();
        {
            float s = tmb1[tid];
            #pragma unroll 4
            for (int k = 0; k < 128; k++) s = fmaf(e[k], tmW1[k * 256 + tid], s);
            hid[tid] = silu_f(s);
        }
        __syncthreads();
        if (tid < 128) {
            float s = tmb2[tid];
            #pragma unroll 4
            for (int k = 0; k < 256; k++) s = fmaf(hid[k], tmW2[k * 128 + tid], s);
            g_temb[g * 128 + tid] = s;
        }
        return;
    }

    int i = blockIdx.x * 256 + tid;

    if (f == 0) {                       // ---- fp16 pack: eW2 + cW1 ----
        if (i >= 2 * NL * 16384) return;
        int mat = i >> 16;
        int r16 = i & 65535;
        int l = r16 >> 14, r14 = r16 & 16383;
        int kb = r14 >> 12, rr = r14 & 4095;
        int q = rr & 7, lane = (rr >> 3) & 31, nf = rr >> 8;
        int k = kb * 32 + (q >> 1) * 8 + (lane & 3) * 2 + (q & 1);
        int n = nf * 8 + (lane >> 2);
        const float* W = (mat == 0 ? eW2 : cW1) + (size_t)l * 16384;
        g_packWh[(size_t)mat * NL * 16384 + r16] = __float2half(W[(size_t)k * 128 + n]);
        return;
    }

    int kb, rr, dstbase;
    const float* src = nullptr;
    if (f == 1) {                       // nW2 tf32
        if (i >= 65536) return;
        int l = i >> 14, r14 = i & 16383;
        kb = r14 >> 12; rr = r14 & 4095;
        src = nW2 + (size_t)l * 16384;
        dstbase = PK_NW2 + l * 16384;
    } else if (f == 2) {
        return;
    } else if (f == 3) {
        if (i >= 196608) return;
        int l = i / 49152, r = i % 49152;
        kb = r >> 12; rr = r & 4095;
        src = nW1 + (size_t)l * 49152;
        dstbase = PK_NW1 + l * 49152;
    } else if (f == 4) {
        if (i >= 20480) {
            if (i < 21504) {
                int idx2 = i - 20480;
                int l = idx2 >> 8, c = idx2 & 255;
                g_biasP[l * 256 + c] = (c < 128) ? eb1[l * 128 + c] : 0.f;
            }
            return;
        }
        kb = i >> 12; rr = i & 4095;
        src = neW;
        dstbase = PK_NE;
    } else {                            // f == 5: folded eW1 -> Wp (tf32)
        if (i >= 262144) return;
        int l = i >> 16, r = i & 65535, slab = r >> 15, r2 = r & 32767;
        kb = r2 >> 12; rr = r2 & 4095;
        int hi = rr >> 7, lo = rr & 127;
        int nf = hi >> 1, ksh = hi & 1;
        int lane = lo >> 2, tb = lo & 3;
        int ks = ksh * 2 + (tb >> 1), pair = tb & 1;
        int k = kb * 32 + ks * 8 + (lane & 3) + pair * 4;
        int n = nf * 8 + (lane >> 2);
        const float* W = eW1 + (size_t)l * 385 * 128;
        float v;
        if (slab == 0) v = (k < 128) ? W[k * 128 + n] : W[(257 + (k - 128)) * 128 + n];
        else           v = (k < 128) ? W[(128 + k) * 128 + n] : 0.f;
        g_packW[PK_WP + (l * 2 + slab) * 32768 + kb * 4096 + rr] = to_tf32(v);
        return;
    }
    int hi = rr >> 7, lo = rr & 127;
    int nf = hi >> 1, ksh = hi & 1;
    int lane = lo >> 2, tb = lo & 3;
    int ks = ksh * 2 + (tb >> 1), pair = tb & 1;
    int k = kb * 32 + ks * 8 + (lane & 3) + pair * 4;
    int n = nf * 8 + (lane >> 2);
    g_packW[dstbase + kb * 4096 + rr] = to_tf32(src[(size_t)k * 128 + n]);
}

// ================= pipelined node GEMM (tf32) =================
// MODE 0: plain; MODE 1: ne (+t-fill/shift-zero); MODE 2: MI ([h|sum12 m|t])
// HOUT: C is __half*; FINAL: prologue copies g_shift -> shift_out
template <int NS, int MODE, bool SILU, bool RES, bool DUAL, bool HOUT, bool FINAL>
__global__ void __launch_bounds__(256) mma_node(
    const float* __restrict__ A0, const void* __restrict__ A1v,
    const float* __restrict__ A2, const int* __restrict__ idxp,
    const int* __restrict__ batch, int ldA,
    const float* __restrict__ W0, const float* __restrict__ W1,
    const float* __restrict__ bias,
    void* __restrict__ Cv, int ldC, float* __restrict__ C2, int ldC2,
    int M, int Kb, const float* __restrict__ Rsrc,
    float* __restrict__ shift_out) {
    extern __shared__ float sm[];
    float* As = sm;
    float* Bs = sm + 4608;
    float* s_bias = Bs + 2 * 4096 * NS;
    int tid = threadIdx.x, w = tid >> 5, lane = tid & 31;
    for (int i = tid; i < NS * 128; i += 256) s_bias[i] = bias[i];
    int m0 = blockIdx.x * 128;
    uint32_t bs_sm = (uint32_t)__cvta_generic_to_shared(Bs);

    if (MODE == 1) {
        for (int idx = tid; idx < 4096; idx += 256) {
            int r = idx >> 5, c4 = idx & 31;
            int row = m0 + r;
            if (row < NN) {
                float4 tv = *(const float4*)(g_temb + (size_t)batch[row] * 128 + c4 * 4);
                *(float4*)(g_X + (size_t)row * 256 + 128 + c4 * 4) = tv;
            }
        }
        if (tid < 128) {
            int row = m0 + tid;
            if (row < NN) {
                g_shift[row * 3 + 0] = 0.f;
                g_shift[row * 3 + 1] = 0.f;
                g_shift[row * 3 + 2] = 0.f;
            }
        }
    }
    if (FINAL) {
        for (int idx = tid; idx < 384; idx += 256) {
            int g = m0 * 3 + idx;
            if (g < NN * 3) shift_out[g] = g_shift[g];
        }
    }

    float acc[NS][16][4];
    #pragma unroll
    for (int s = 0; s < NS; s++)
        #pragma unroll
        for (int nf = 0; nf < 16; nf++)
            #pragma unroll
            for (int j = 0; j < 4; j++) acc[s][nf][j] = 0.f;

    float4 av[4];
    auto ldA_regs = [&](int kb) {
        #pragma unroll
        for (int i = 0; i < 4; i++) {
            int idx = tid + i * 256;
            int r = idx >> 3, c4 = idx & 7;
            int row = m0 + r;
            float4 v = make_float4(0.f, 0.f, 0.f, 0.f);
            if (row < M) {
                if (MODE == 0) {
                    v = *(const float4*)(A0 + (size_t)row * ldA + kb * 32 + c4 * 4);
                } else if (MODE == 1) {
                    if (kb < 4) v = *(const float4*)(A0 + (size_t)row * 128 + kb * 32 + c4 * 4);
                    else        v = *(const float4*)((const float*)A1v + (size_t)idxp[row] * 32 + c4 * 4);
                } else {
                    if (kb < 4) {
                        v = *(const float4*)(A0 + (size_t)row * 128 + kb * 32 + c4 * 4);
                    } else if (kb < 8) {
                        const __half* Mh = (const __half*)A1v;
                        const __half* base = Mh + (size_t)row * KNB * 128 + (kb - 4) * 32 + c4 * 4;
                        #pragma unroll
                        for (int j = 0; j < KNB; j++) {
                            uint2 u = *(const uint2*)(base + (size_t)j * 128);
                            __half2 h0 = *(__half2*)&u.x;
                            __half2 h1 = *(__half2*)&u.y;
                            float2 f0 = __half22float2(h0);
                            float2 f1 = __half22float2(h1);
                            v.x += f0.x; v.y += f0.y; v.z += f1.x; v.w += f1.y;
                        }
                    } else {
                        v = *(const float4*)(A2 + (size_t)row * 256 + (kb - 8) * 32 + c4 * 4);
                    }
                }
            }
            av[i] = v;
        }
    };
    auto stA = [&]() {
        #pragma unroll
        for (int i = 0; i < 4; i++) {
            int idx = tid + i * 256;
            int r = idx >> 3, c4 = idx & 7;
            float4 v;
            v.x = to_tf32(av[i].x); v.y = to_tf32(av[i].y);
            v.z = to_tf32(av[i].z); v.w = to_tf32(av[i].w);
            *(float4*)(As + r * 36 + c4 * 4) = v;
        }
    };
    auto cpB = [&](int kb, int buf) {
        uint32_t dst = bs_sm + buf * (4096 * NS) * 4;
        const float* s0 = W0 + (size_t)kb * 4096;
        #pragma unroll
        for (int j = 0; j < 4; j++)
            cp16(dst + (tid + j * 256) * 16, s0 + (tid + j * 256) * 4);
        if constexpr (NS == 2) {
            const float* s1 = W1 + (size_t)kb * 4096;
            #pragma unroll
            for (int j = 0; j < 4; j++)
                cp16(dst + 16384 + (tid + j * 256) * 16, s1 + (tid + j * 256) * 4);
        }
        CP_COMMIT();
    };

    ldA_regs(0);
    cpB(0, 0);
    for (int kb = 0; kb < Kb; kb++) {
        int cur = kb & 1;
        stA();
        if (kb + 1 < Kb) {
            cpB(kb + 1, cur ^ 1);
            ldA_regs(kb + 1);
            CP_WAIT1();
        } else {
            CP_WAIT0();
        }
        __syncthreads();
        const float* Bb = Bs + cur * (4096 * NS);
        #pragma unroll
        for (int ksh = 0; ksh < 2; ksh++) {
            const float* ap = As + (w * 16 + (lane >> 2)) * 36 + ksh * 16 + (lane & 3);
            uint32_t p00 = __float_as_uint(ap[0]);
            uint32_t p01 = __float_as_uint(ap[8 * 36]);
            uint32_t p02 = __float_as_uint(ap[4]);
            uint32_t p03 = __float_as_uint(ap[8 * 36 + 4]);
            uint32_t p10 = __float_as_uint(ap[8]);
            uint32_t p11 = __float_as_uint(ap[8 * 36 + 8]);
            uint32_t p12 = __float_as_uint(ap[12]);
            uint32_t p13 = __float_as_uint(ap[8 * 36 + 12]);
            #pragma unroll
            for (int nf = 0; nf < 16; nf++) {
                float4 b = *(const float4*)(Bb + (nf * 2 + ksh) * 128 + lane * 4);
                mma_tf32(acc[0][nf], p00, p01, p02, p03,
                         __float_as_uint(b.x), __float_as_uint(b.y));
                mma_tf32(acc[0][nf], p10, p11, p12, p13,
                         __float_as_uint(b.z), __float_as_uint(b.w));
                if constexpr (NS == 2) {
                    float4 b1v = *(const float4*)(Bb + 4096 + (nf * 2 + ksh) * 128 + lane * 4);
                    mma_tf32(acc[1][nf], p00, p01, p02, p03,
                             __float_as_uint(b1v.x), __float_as_uint(b1v.y));
                    mma_tf32(acc[1][nf], p10, p11, p12, p13,
                             __float_as_uint(b1v.z), __float_as_uint(b1v.w));
                }
            }
        }
        __syncthreads();
    }

    int r0 = w * 16 + (lane >> 2);
    int row0 = m0 + r0, row1 = row0 + 8;
    #pragma unroll
    for (int s = 0; s < NS; s++) {
        #pragma unroll
        for (int nf = 0; nf < 16; nf++) {
            int lc = nf * 8 + (lane & 3) * 2;
            int col = s * 128 + lc;
            float v0 = acc[s][nf][0] + s_bias[col];
            float v1 = acc[s][nf][1] + s_bias[col + 1];
            float v2 = acc[s][nf][2] + s_bias[col];
            float v3 = acc[s][nf][3] + s_bias[col + 1];
            if (SILU) { v0 = silu_f(v0); v1 = silu_f(v1); v2 = silu_f(v2); v3 = silu_f(v3); }
            if constexpr (HOUT) {
                __half* Ch = (__half*)Cv;
                if (row0 < M)
                    *(uint32_t*)(Ch + (size_t)row0 * ldC + col) = f2h2(v0, v1);
                if (row1 < M)
                    *(uint32_t*)(Ch + (size_t)row1 * ldC + col) = f2h2(v2, v3);
            } else {
                float* C = (float*)Cv;
                if (row0 < M) {
                    if (RES) {
                        float2 r = *(const float2*)(Rsrc + (size_t)row0 * 128 + col);
                        v0 += r.x; v1 += r.y;
                    }
                    *(float2*)(C + (size_t)row0 * ldC + col) = make_float2(v0, v1);
                    if (DUAL) *(float2*)(C2 + (size_t)row0 * ldC2 + col) = make_float2(v0, v1);
                }
                if (row1 < M) {
                    if (RES) {
                        float2 r = *(const float2*)(Rsrc + (size_t)row1 * 128 + col);
                        v2 += r.x; v3 += r.y;
                    }
                    *(float2*)(C + (size_t)row1 * ldC + col) = make_float2(v2, v3);
                    if (DUAL) *(float2*)(C2 + (size_t)row1 * ldC2 + col) = make_float2(v2, v3);
                }
            }
        }
    }
}
#define NODE_SMEM1 51712
#define NODE_SMEM2 84992

// ================= fused edge kernel: all-resident smem, barrier-free GEMMs =================
// smem bytes: Ah 128x136h = 34816 | Bw 32768 | Bc 32768 | gate 1024 | meta 3584 -> 104960
#define EDGE_SMEM 104960
__global__ void __launch_bounds__(256, 2) mma_edge(
    const int* __restrict__ esrc, const int* __restrict__ edst,
    const float* __restrict__ coords, const __half* __restrict__ P,
    const float* __restrict__ wc, const float* __restrict__ eb2,
    const __half* __restrict__ w2pk, const __half* __restrict__ c1pk,
    const float* __restrict__ cb1, const float* __restrict__ cw2) {
    extern __shared__ char smc[];
    __half* Ah    = (__half*)smc;                 // 128 x 136 halves
    __half* Bw    = (__half*)(smc + 34816);       // 16384 halves (eW2, all K)
    __half* Bc    = (__half*)(smc + 67584);       // 16384 halves (cW1, all K)
    float* s_gate = (float*)(smc + 100352);       // 256
    int* s_src    = (int*)(smc + 101376);
    int* s_dst    = (int*)(smc + 101888);
    float* s_ds   = (float*)(smc + 102400);
    float* s_wc   = (float*)(smc + 102912);
    float* s_eb2  = (float*)(smc + 103424);
    float* s_cb1  = (float*)(smc + 103936);
    float* s_cw2  = (float*)(smc + 104448);
    int tid = threadIdx.x, w = tid >> 5, lane = tid & 31;
    int wr = w & 3, cg = w >> 2;
    uint32_t bw_sm = (uint32_t)__cvta_generic_to_shared(Bw);
    uint32_t bc_sm = (uint32_t)__cvta_generic_to_shared(Bc);
    int ebase = blockIdx.x * 128;

    // ---- one-shot cp.async of BOTH full weight matrices ----
    #pragma unroll
    for (int j = 0; j < 8; j++)
        cp16(bw_sm + (tid + j * 256) * 16, w2pk + (tid + j * 256) * 8);
    #pragma unroll
    for (int j = 0; j < 8; j++)
        cp16(bc_sm + (tid + j * 256) * 16, c1pk + (tid + j * 256) * 8);
    CP_COMMIT();

    if (tid < 128) {
        int e = ebase + tid;
        int s = esrc[e], d = edst[e];
        s_src[tid] = s; s_dst[tid] = d;
        float dx = coords[s * 3 + 0] - coords[d * 3 + 0];
        float dy = coords[s * 3 + 1] - coords[d * 3 + 1];
        float dz = coords[s * 3 + 2] - coords[d * 3 + 2];
        s_ds[tid] = dx * dx + dy * dy + dz * dz;
        s_wc[tid] = wc[tid];
        s_eb2[tid] = eb2[tid];
        s_cb1[tid] = cb1[tid];
        s_cw2[tid] = cw2[tid];
    }
    __syncthreads();

    // ---- build full A = fp16(silu(P_src + P_dst + ds*wc)) in smem ----
    #pragma unroll
    for (int kb = 0; kb < 4; kb++) {
        #pragma unroll
        for (int i = 0; i < 2; i++) {
            int idx = tid + i * 256;
            int r = idx >> 2, c8 = idx & 3;
            int s = s_src[r], d = s_dst[r];
            float ds = s_ds[r];
            uint4 us = *(const uint4*)(P + (size_t)s * 256 + kb * 32 + c8 * 8);
            uint4 ud = *(const uint4*)(P + (size_t)d * 256 + 128 + kb * 32 + c8 * 8);
            const float* Wv = s_wc + kb * 32 + c8 * 8;
            float4 w0 = *(const float4*)Wv, w1 = *(const float4*)(Wv + 4);
            float2 s0 = __half22float2(*(__half2*)&us.x);
            float2 s1 = __half22float2(*(__half2*)&us.y);
            float2 s2 = __half22float2(*(__half2*)&us.z);
            float2 s3 = __half22float2(*(__half2*)&us.w);
            float2 d0 = __half22float2(*(__half2*)&ud.x);
            float2 d1 = __half22float2(*(__half2*)&ud.y);
            float2 d2 = __half22float2(*(__half2*)&ud.z);
            float2 d3 = __half22float2(*(__half2*)&ud.w);
            uint4 v;
            v.x = f2h2(silu_f(s0.x + d0.x + ds * w0.x), silu_f(s0.y + d0.y + ds * w0.y));
            v.y = f2h2(silu_f(s1.x + d1.x + ds * w0.z), silu_f(s1.y + d1.y + ds * w0.w));
            v.z = f2h2(silu_f(s2.x + d2.x + ds * w1.x), silu_f(s2.y + d2.y + ds * w1.y));
            v.w = f2h2(silu_f(s3.x + d3.x + ds * w1.z), silu_f(s3.y + d3.y + ds * w1.w));
            *(uint4*)(Ah + r * 136 + kb * 32 + c8 * 8) = v;
        }
    }
    CP_WAIT0();
    __syncthreads();

    float acc[2][8][4];
    #pragma unroll
    for (int mf = 0; mf < 2; mf++)
        #pragma unroll
        for (int nf = 0; nf < 8; nf++)
            #pragma unroll
            for (int j = 0; j < 4; j++) acc[mf][nf][j] = 0.f;

    // barrier-free full-K GEMM from resident smem
    auto gemm_full = [&](const __half* Bb) {
        #pragma unroll
        for (int kb = 0; kb < 4; kb++) {
            uint32_t Areg[2][2][4];
            const __half* ap = Ah + (wr * 32 + (lane >> 2)) * 136 + kb * 32 + (lane & 3) * 2;
            #pragma unroll
            for (int mf = 0; mf < 2; mf++) {
                const __half* base = ap + mf * 16 * 136;
                #pragma unroll
                for (int ks = 0; ks < 2; ks++) {
                    const __half* p = base + ks * 16;
                    Areg[mf][ks][0] = *(const uint32_t*)(p);
                    Areg[mf][ks][1] = *(const uint32_t*)(p + 8 * 136);
                    Areg[mf][ks][2] = *(const uint32_t*)(p + 8);
                    Areg[mf][ks][3] = *(const uint32_t*)(p + 8 * 136 + 8);
                }
            }
            const __half* Bkb = Bb + kb * 4096;
            #pragma unroll
            for (int nf = 0; nf < 8; nf++) {
                uint4 bv = *(const uint4*)(Bkb + ((cg * 8 + nf) * 32 + lane) * 8);
                #pragma unroll
                for (int mf = 0; mf < 2; mf++) {
                    mma_f16(acc[mf][nf], Areg[mf][0][0], Areg[mf][0][1], Areg[mf][0][2], Areg[mf][0][3],
                            bv.x, bv.y);
                    mma_f16(acc[mf][nf], Areg[mf][1][0], Areg[mf][1][1], Areg[mf][1][2], Areg[mf][1][3],
                            bv.z, bv.w);
                }
            }
        }
    };

    // ---- GEMM 1: pre @ eW2 (no barriers) ----
    gemm_full(Bw);
    __syncthreads();   // peer cg warp must finish reading shared A rows

    // ---- epilogue 1: m = fp16(silu(.+eb2)) -> g_M and in-place into Ah ----
    int r0 = wr * 32 + (lane >> 2);
    int e0 = ebase + r0;
    #pragma unroll
    for (int mf = 0; mf < 2; mf++) {
        int ea = e0 + mf * 16;
        int ra = r0 + mf * 16;
        #pragma unroll
        for (int nf = 0; nf < 8; nf++) {
            int col = cg * 64 + nf * 8 + (lane & 3) * 2;
            float m0 = silu_f(acc[mf][nf][0] + s_eb2[col]);
            float m1 = silu_f(acc[mf][nf][1] + s_eb2[col + 1]);
            float m2 = silu_f(acc[mf][nf][2] + s_eb2[col]);
            float m3 = silu_f(acc[mf][nf][3] + s_eb2[col + 1]);
            uint32_t h01 = f2h2(m0, m1), h23 = f2h2(m2, m3);
            *(uint32_t*)(g_M + (size_t)ea * 128 + col)       = h01;
            *(uint32_t*)(g_M + (size_t)(ea + 8) * 128 + col) = h23;
            *(uint32_t*)(Ah + ra * 136 + col)       = h01;
            *(uint32_t*)(Ah + (ra + 8) * 136 + col) = h23;
            acc[mf][nf][0] = 0.f; acc[mf][nf][1] = 0.f;
            acc[mf][nf][2] = 0.f; acc[mf][nf][3] = 0.f;
        }
    }
    __syncthreads();   // A rewrite visible to peer cg warp

    // ---- GEMM 2: m @ cW1 (all from smem, no barriers) ----
    gemm_full(Bc);

    // ---- epilogue 2: gate + fused shift atomics ----
    float gp[4] = {0.f, 0.f, 0.f, 0.f};
    #pragma unroll
    for (int mf = 0; mf < 2; mf++) {
        #pragma unroll
        for (int nf = 0; nf < 8; nf++) {
            int col = cg * 64 + nf * 8 + (lane & 3) * 2;
            gp[mf * 2]     += silu_f(acc[mf][nf][0] + s_cb1[col]) * s_cw2[col]
                            + silu_f(acc[mf][nf][1] + s_cb1[col + 1]) * s_cw2[col + 1];
            gp[mf * 2 + 1] += silu_f(acc[mf][nf][2] + s_cb1[col]) * s_cw2[col]
                            + silu_f(acc[mf][nf][3] + s_cb1[col + 1]) * s_cw2[col + 1];
        }
    }
    #pragma unroll
    for (int j = 0; j < 4; j++) {
        gp[j] += __shfl_xor_sync(0xffffffffu, gp[j], 1);
        gp[j] += __shfl_xor_sync(0xffffffffu, gp[j], 2);
    }
    if ((lane & 3) == 0) {
        int rl = wr * 32 + (lane >> 2);
        s_gate[rl * 2 + cg]        = gp[0];
        s_gate[(rl + 8) * 2 + cg]  = gp[1];
        s_gate[(rl + 16) * 2 + cg] = gp[2];
        s_gate[(rl + 24) * 2 + cg] = gp[3];
    }
    __syncthreads();
    if (tid < 128) {
        float gt = s_gate[tid * 2] + s_gate[tid * 2 + 1];
        int s = s_src[tid], d = s_dst[tid];
        float dx = coords[s * 3 + 0] - coords[d * 3 + 0];
        float dy = coords[s * 3 + 1] - coords[d * 3 + 1];
        float dz = coords[s * 3 + 2] - coords[d * 3 + 2];
        float q = gt * __frsqrt_rn(s_ds[tid] + 1e-8f);
        atomicAdd(&g_shift[d * 3 + 0], dx * q);
        atomicAdd(&g_shift[d * 3 + 1], dy * q);
        atomicAdd(&g_shift[d * 3 + 2], dz * q);
    }
}

// ================= host =================
extern "C" void kernel_launch(void* const* d_in, const int* in_sizes, int n_in,
                              void* d_out, int out_size) {
    const float* z      = (const float*)d_in[0];
    const float* t      = (const float*)d_in[1];
    const float* coords = (const float*)d_in[2];
    const int*   species= (const int*)d_in[3];
    const int*   batch  = (const int*)d_in[4];
    const int*   esrc   = (const int*)d_in[5];
    const int*   edst   = (const int*)d_in[6];
    const float* spemb  = (const float*)d_in[7];
    const float* tmW1   = (const float*)d_in[8];
    const float* tmb1   = (const float*)d_in[9];
    const float* tmW2   = (const float*)d_in[10];
    const float* tmb2   = (const float*)d_in[11];
    const float* neW    = (const float*)d_in[12];
    const float* neb    = (const float*)d_in[13];
    const float* eW1    = (const float*)d_in[14];
    const float* eb1    = (const float*)d_in[15];
    const float* eW2    = (const float*)d_in[16];
    const float* eb2    = (const float*)d_in[17];
    const float* cW1    = (const float*)d_in[18];
    const float* cb1    = (const float*)d_in[19];
    const float* cW2    = (const float*)d_in[20];
    const float* nW1    = (const float*)d_in[21];
    const float* nb1    = (const float*)d_in[22];
    const float* nW2    = (const float*)d_in[23];
    const float* nb2    = (const float*)d_in[24];
    float* out = (float*)d_out;

    float *pX, *pU, *pH, *pPk, *pBiasP;
    __half *pM, *pP, *pPkh;
    cudaGetSymbolAddress((void**)&pX,    g_X);
    cudaGetSymbolAddress((void**)&pP,    g_P);
    cudaGetSymbolAddress((void**)&pU,    g_u);
    cudaGetSymbolAddress((void**)&pH,    g_h);
    cudaGetSymbolAddress((void**)&pM,    g_M);
    cudaGetSymbolAddress((void**)&pPk,   g_packW);
    cudaGetSymbolAddress((void**)&pPkh,  g_packWh);
    cudaGetSymbolAddress((void**)&pBiasP, g_biasP);

    cudaFuncSetAttribute(mma_edge, cudaFuncAttributeMaxDynamicSharedMemorySize, EDGE_SMEM);
    cudaFuncSetAttribute(mma_node<1,1,false,false,true,false,false>,  cudaFuncAttributeMaxDynamicSharedMemorySize, NODE_SMEM1);
    cudaFuncSetAttribute(mma_node<2,0,false,false,false,true,false>,  cudaFuncAttributeMaxDynamicSharedMemorySize, NODE_SMEM2);
    cudaFuncSetAttribute(mma_node<1,2,true,false,false,false,false>,  cudaFuncAttributeMaxDynamicSharedMemorySize, NODE_SMEM1);
    cudaFuncSetAttribute(mma_node<1,0,false,true,true,false,false>,   cudaFuncAttributeMaxDynamicSharedMemorySize, NODE_SMEM1);
    cudaFuncSetAttribute(mma_node<1,0,false,true,false,false,true>,   cudaFuncAttributeMaxDynamicSharedMemorySize, NODE_SMEM1);

    const int MT = (NN + 127) / 128;   // 157

    setup_kernel<<<dim3(1024, 7), 256>>>(eW2, cW1, nW2, nW1, neW, eW1, eb1,
                                         t, tmW1, tmb1, tmW2, tmb2);
    // h0 = [z|sp] @ neW + neb  (dual-store h, X[:, :128])
    mma_node<1, 1, false, false, true, false, false><<<MT, 256, NODE_SMEM1>>>(
        z, spemb, nullptr, species, batch, 128,
        pPk + PK_NE, nullptr, neb, pH, 128, pX, 256, NN, 5, nullptr, nullptr);

    for (int l = 0; l < NL; l++) {
        // P = [h|t] @ Wp  -> fp16 g_P
        mma_node<2, 0, false, false, false, true, false><<<MT, 256, NODE_SMEM2>>>(
            pX, nullptr, nullptr, nullptr, nullptr, 256,
            pPk + PK_WP + (l * 2 + 0) * 32768, pPk + PK_WP + (l * 2 + 1) * 32768,
            pBiasP + l * 256, pP, 256, nullptr, 0, NN, 8, nullptr, nullptr);
        // fused edge: m + gate + shift
        mma_edge<<<NE / 128, 256, EDGE_SMEM>>>(
            esrc, edst, coords, pP,
            eW1 + (size_t)l * 385 * 128 + 256 * 128, eb2 + l * 128,
            pPkh + (size_t)l * 16384, pPkh + (size_t)(NL + l) * 16384,
            cb1 + l * 128, cW2 + l * 128);
        // u = silu([h | sum12 m | t] @ nW1 + nb1)
        mma_node<1, 2, true, false, false, false, false><<<MT, 256, NODE_SMEM1>>>(
            pH, pM, pX + 128, nullptr, nullptr, 0,
            pPk + PK_NW1 + l * 49152, nullptr, nb1 + l * 128,
            pU, 128, nullptr, 0, NN, 12, nullptr, nullptr);
        if (l < NL - 1) {
            // h = h + u @ nW2 + nb2  (dual-store h, X)
            mma_node<1, 0, false, true, true, false, false><<<MT, 256, NODE_SMEM1>>>(
                pU, nullptr, nullptr, nullptr, nullptr, 128,
                pPk + PK_NW2 + l * 16384, nullptr, nb2 + l * 128,
                pH, 128, pX, 256, NN, 4, pH, nullptr);
        } else {
            // final: h -> out[NN*3 + ...], shift -> out[0:NN*3]
            mma_node<1, 0, false, true, false, false, true><<<MT, 256, NODE_SMEM1>>>(
                pU, nullptr, nullptr, nullptr, nullptr, 128,
                pPk + PK_NW2 + l * 16384, nullptr, nb2 + l * 128,
                out + NN * 3, 128, nullptr, 0, NN, 4, pH, out);
        }
    }
}

// round 16
// speedup vs baseline: 1.1730x; 1.0912x over previous
#include <cuda_runtime.h>
#include <cuda_fp16.h>
#include <math.h>
#include <stdint.h>

#define NN 20000
#define NG 400
#define KNB 12
#define NE 240000
#define NL 4

// ---- packed tf32 weight region offsets (floats) ----
#define PK_NW2 131072
#define PK_NW1 196608
#define PK_NE  393216
#define PK_WP  413696
#define PK_TOTAL 675840

// ---- static device scratch ----
__device__ float g_temb[NG * 128];
__device__ float g_h[NN * 128];
__device__ float g_X[NN * 256];      // [h | t]
__device__ __half g_P[NN * 256];     // fp16 P
__device__ __half g_M[NE * 128];     // fp16 messages
__device__ float g_u[NN * 128];
__device__ float g_packW[PK_TOTAL];          // tf32 fragment images (node)
__device__ __half g_packWh[2 * NL * 16384];  // fp16 fragment images: [eW2 | cW1]
__device__ float g_biasP[NL * 256];
__device__ float g_shift[NN * 3];

__device__ __forceinline__ float silu_f(float x) {
    return __fdividef(x, 1.0f + __expf(-x));
}
__device__ __forceinline__ float to_tf32(float x) {
    float r; asm("cvt.rna.tf32.f32 %0, %1;" : "=f"(r) : "f"(x)); return r;
}
__device__ __forceinline__ uint32_t f2h2(float a, float b) {
    __half2 h = __floats2half2_rn(a, b);
    return *(uint32_t*)&h;
}

__device__ __forceinline__ void mma_tf32(float c[4], uint32_t a0, uint32_t a1,
                                         uint32_t a2, uint32_t a3,
                                         uint32_t b0, uint32_t b1) {
    asm volatile(
        "mma.sync.aligned.m16n8k8.row.col.f32.tf32.tf32.f32 "
        "{%0,%1,%2,%3}, {%4,%5,%6,%7}, {%8,%9}, {%0,%1,%2,%3};"
        : "+f"(c[0]), "+f"(c[1]), "+f"(c[2]), "+f"(c[3])
        : "r"(a0), "r"(a1), "r"(a2), "r"(a3), "r"(b0), "r"(b1));
}
__device__ __forceinline__ void mma_f16(float c[4], uint32_t a0, uint32_t a1,
                                        uint32_t a2, uint32_t a3,
                                        uint32_t b0, uint32_t b1) {
    asm volatile(
        "mma.sync.aligned.m16n8k16.row.col.f32.f16.f16.f32 "
        "{%0,%1,%2,%3}, {%4,%5,%6,%7}, {%8,%9}, {%0,%1,%2,%3};"
        : "+f"(c[0]), "+f"(c[1]), "+f"(c[2]), "+f"(c[3])
        : "r"(a0), "r"(a1), "r"(a2), "r"(a3), "r"(b0), "r"(b1));
}

__device__ __forceinline__ void cp16(uint32_t saddr, const void* g) {
    asm volatile("cp.async.ca.shared.global [%0], [%1], 16;" :: "r"(saddr), "l"(g));
}
#define CP_COMMIT() asm volatile("cp.async.commit_group;" ::: "memory")
#define CP_WAIT1()  asm volatile("cp.async.wait_group 1;" ::: "memory")
#define CP_WAIT0()  asm volatile("cp.async.wait_group 0;" ::: "memory")

// tf32 B layout per 32-K block (4096 fl): pos=(nf*2+(ks>>1))*128+lane*4+(ks&1)*2+pair
// fp16 B layout per 32-K block (4096 h): pos=(nf*32+lane)*8+q

// ================= launch 0: setup = pack + temb =================
__global__ void setup_kernel(const float* __restrict__ eW2, const float* __restrict__ cW1,
                             const float* __restrict__ nW2, const float* __restrict__ nW1,
                             const float* __restrict__ neW, const float* __restrict__ eW1,
                             const float* __restrict__ eb1,
                             const float* __restrict__ t,
                             const float* __restrict__ tmW1, const float* __restrict__ tmb1,
                             const float* __restrict__ tmW2, const float* __restrict__ tmb2) {
    int f = blockIdx.y;
    int tid = threadIdx.x;

    if (f == 6) {                       // ---- time-embedding MLP ----
        int g = blockIdx.x;
        if (g >= NG) return;
        __shared__ float e[128];
        __shared__ float hid[256];
        float tv = t[g];
        if (tid < 64) {
            float fr = expf(-(float)tid * (logf(10000.0f) / 63.0f));
            float a = tv * fr;
            e[tid] = sinf(a); e[tid + 64] = cosf(a);
        }
        __syncthreads();
        {
            float s = tmb1[tid];
            #pragma unroll 4
            for (int k = 0; k < 128; k++) s = fmaf(e[k], tmW1[k * 256 + tid], s);
            hid[tid] = silu_f(s);
        }
        __syncthreads();
        if (tid < 128) {
            float s = tmb2[tid];
            #pragma unroll 4
            for (int k = 0; k < 256; k++) s = fmaf(hid[k], tmW2[k * 128 + tid], s);
            g_temb[g * 128 + tid] = s;
        }
        return;
    }

    int i = blockIdx.x * 256 + tid;

    if (f == 0) {                       // ---- fp16 pack: eW2 + cW1 ----
        if (i >= 2 * NL * 16384) return;
        int mat = i >> 16;
        int r16 = i & 65535;
        int l = r16 >> 14, r14 = r16 & 16383;
        int kb = r14 >> 12, rr = r14 & 4095;
        int q = rr & 7, lane = (rr >> 3) & 31, nf = rr >> 8;
        int k = kb * 32 + (q >> 1) * 8 + (lane & 3) * 2 + (q & 1);
        int n = nf * 8 + (lane >> 2);
        const float* W = (mat == 0 ? eW2 : cW1) + (size_t)l * 16384;
        g_packWh[(size_t)mat * NL * 16384 + r16] = __float2half(W[(size_t)k * 128 + n]);
        return;
    }

    int kb, rr, dstbase;
    const float* src = nullptr;
    if (f == 1) {                       // nW2 tf32
        if (i >= 65536) return;
        int l = i >> 14, r14 = i & 16383;
        kb = r14 >> 12; rr = r14 & 4095;
        src = nW2 + (size_t)l * 16384;
        dstbase = PK_NW2 + l * 16384;
    } else if (f == 2) {
        return;
    } else if (f == 3) {
        if (i >= 196608) return;
        int l = i / 49152, r = i % 49152;
        kb = r >> 12; rr = r & 4095;
        src = nW1 + (size_t)l * 49152;
        dstbase = PK_NW1 + l * 49152;
    } else if (f == 4) {
        if (i >= 20480) {
            if (i < 21504) {
                int idx2 = i - 20480;
                int l = idx2 >> 8, c = idx2 & 255;
                g_biasP[l * 256 + c] = (c < 128) ? eb1[l * 128 + c] : 0.f;
            }
            return;
        }
        kb = i >> 12; rr = i & 4095;
        src = neW;
        dstbase = PK_NE;
    } else {                            // f == 5: folded eW1 -> Wp (tf32)
        if (i >= 262144) return;
        int l = i >> 16, r = i & 65535, slab = r >> 15, r2 = r & 32767;
        kb = r2 >> 12; rr = r2 & 4095;
        int hi = rr >> 7, lo = rr & 127;
        int nf = hi >> 1, ksh = hi & 1;
        int lane = lo >> 2, tb = lo & 3;
        int ks = ksh * 2 + (tb >> 1), pair = tb & 1;
        int k = kb * 32 + ks * 8 + (lane & 3) + pair * 4;
        int n = nf * 8 + (lane >> 2);
        const float* W = eW1 + (size_t)l * 385 * 128;
        float v;
        if (slab == 0) v = (k < 128) ? W[k * 128 + n] : W[(257 + (k - 128)) * 128 + n];
        else           v = (k < 128) ? W[(128 + k) * 128 + n] : 0.f;
        g_packW[PK_WP + (l * 2 + slab) * 32768 + kb * 4096 + rr] = to_tf32(v);
        return;
    }
    int hi = rr >> 7, lo = rr & 127;
    int nf = hi >> 1, ksh = hi & 1;
    int lane = lo >> 2, tb = lo & 3;
    int ks = ksh * 2 + (tb >> 1), pair = tb & 1;
    int k = kb * 32 + ks * 8 + (lane & 3) + pair * 4;
    int n = nf * 8 + (lane >> 2);
    g_packW[dstbase + kb * 4096 + rr] = to_tf32(src[(size_t)k * 128 + n]);
}

// ================= pipelined node GEMM (tf32), 64-row tiles =================
// 8 warps = 4 rowgroups x 2 colgroups; grid = (NN+63)/64
// MODE 0: plain; MODE 1: ne (+t-fill/shift-zero); MODE 2: MI ([h|sum12 m|t])
// HOUT: C is __half*; FINAL: prologue copies g_shift -> shift_out
template <int NS, int MODE, bool SILU, bool RES, bool DUAL, bool HOUT, bool FINAL>
__global__ void __launch_bounds__(256, (NS == 1) ? 3 : 2) mma_node(
    const float* __restrict__ A0, const void* __restrict__ A1v,
    const float* __restrict__ A2, const int* __restrict__ idxp,
    const int* __restrict__ batch, int ldA,
    const float* __restrict__ W0, const float* __restrict__ W1,
    const float* __restrict__ bias,
    void* __restrict__ Cv, int ldC, float* __restrict__ C2, int ldC2,
    int M, int Kb, const float* __restrict__ Rsrc,
    float* __restrict__ shift_out) {
    extern __shared__ float sm[];
    float* As = sm;                       // 64 x 36 = 2304 floats
    float* Bs = sm + 2304;
    float* s_bias = Bs + 2 * 4096 * NS;
    int tid = threadIdx.x, w = tid >> 5, lane = tid & 31;
    int wr = w & 3, cg = w >> 2;
    for (int i = tid; i < NS * 128; i += 256) s_bias[i] = bias[i];
    int m0 = blockIdx.x * 64;
    uint32_t bs_sm = (uint32_t)__cvta_generic_to_shared(Bs);

    if (MODE == 1) {
        for (int idx = tid; idx < 2048; idx += 256) {
            int r = idx >> 5, c4 = idx & 31;
            int row = m0 + r;
            if (row < NN) {
                float4 tv = *(const float4*)(g_temb + (size_t)batch[row] * 128 + c4 * 4);
                *(float4*)(g_X + (size_t)row * 256 + 128 + c4 * 4) = tv;
            }
        }
        if (tid < 64) {
            int row = m0 + tid;
            if (row < NN) {
                g_shift[row * 3 + 0] = 0.f;
                g_shift[row * 3 + 1] = 0.f;
                g_shift[row * 3 + 2] = 0.f;
            }
        }
    }
    if (FINAL) {
        if (tid < 192) {
            int g = m0 * 3 + tid;
            if (g < NN * 3) shift_out[g] = g_shift[g];
        }
    }

    float acc[NS][8][4];
    #pragma unroll
    for (int s = 0; s < NS; s++)
        #pragma unroll
        for (int nf = 0; nf < 8; nf++)
            #pragma unroll
            for (int j = 0; j < 4; j++) acc[s][nf][j] = 0.f;

    float4 av[2];
    auto ldA_regs = [&](int kb) {
        #pragma unroll
        for (int i = 0; i < 2; i++) {
            int idx = tid + i * 256;
            int r = idx >> 3, c4 = idx & 7;
            int row = m0 + r;
            float4 v = make_float4(0.f, 0.f, 0.f, 0.f);
            if (row < M) {
                if (MODE == 0) {
                    v = *(const float4*)(A0 + (size_t)row * ldA + kb * 32 + c4 * 4);
                } else if (MODE == 1) {
                    if (kb < 4) v = *(const float4*)(A0 + (size_t)row * 128 + kb * 32 + c4 * 4);
                    else        v = *(const float4*)((const float*)A1v + (size_t)idxp[row] * 32 + c4 * 4);
                } else {
                    if (kb < 4) {
                        v = *(const float4*)(A0 + (size_t)row * 128 + kb * 32 + c4 * 4);
                    } else if (kb < 8) {
                        const __half* Mh = (const __half*)A1v;
                        const __half* base = Mh + (size_t)row * KNB * 128 + (kb - 4) * 32 + c4 * 4;
                        #pragma unroll
                        for (int j = 0; j < KNB; j++) {
                            uint2 u = *(const uint2*)(base + (size_t)j * 128);
                            __half2 h0 = *(__half2*)&u.x;
                            __half2 h1 = *(__half2*)&u.y;
                            float2 f0 = __half22float2(h0);
                            float2 f1 = __half22float2(h1);
                            v.x += f0.x; v.y += f0.y; v.z += f1.x; v.w += f1.y;
                        }
                    } else {
                        v = *(const float4*)(A2 + (size_t)row * 256 + (kb - 8) * 32 + c4 * 4);
                    }
                }
            }
            av[i] = v;
        }
    };
    auto stA = [&]() {
        #pragma unroll
        for (int i = 0; i < 2; i++) {
            int idx = tid + i * 256;
            int r = idx >> 3, c4 = idx & 7;
            float4 v;
            v.x = to_tf32(av[i].x); v.y = to_tf32(av[i].y);
            v.z = to_tf32(av[i].z); v.w = to_tf32(av[i].w);
            *(float4*)(As + r * 36 + c4 * 4) = v;
        }
    };
    auto cpB = [&](int kb, int buf) {
        uint32_t dst = bs_sm + buf * (4096 * NS) * 4;
        const float* s0 = W0 + (size_t)kb * 4096;
        #pragma unroll
        for (int j = 0; j < 4; j++)
            cp16(dst + (tid + j * 256) * 16, s0 + (tid + j * 256) * 4);
        if constexpr (NS == 2) {
            const float* s1 = W1 + (size_t)kb * 4096;
            #pragma unroll
            for (int j = 0; j < 4; j++)
                cp16(dst + 16384 + (tid + j * 256) * 16, s1 + (tid + j * 256) * 4);
        }
        CP_COMMIT();
    };

    ldA_regs(0);
    cpB(0, 0);
    for (int kb = 0; kb < Kb; kb++) {
        int cur = kb & 1;
        stA();
        if (kb + 1 < Kb) {
            cpB(kb + 1, cur ^ 1);
            ldA_regs(kb + 1);
            CP_WAIT1();
        } else {
            CP_WAIT0();
        }
        __syncthreads();
        const float* Bb = Bs + cur * (4096 * NS);
        #pragma unroll
        for (int ksh = 0; ksh < 2; ksh++) {
            const float* ap = As + (wr * 16 + (lane >> 2)) * 36 + ksh * 16 + (lane & 3);
            uint32_t p00 = __float_as_uint(ap[0]);
            uint32_t p01 = __float_as_uint(ap[8 * 36]);
            uint32_t p02 = __float_as_uint(ap[4]);
            uint32_t p03 = __float_as_uint(ap[8 * 36 + 4]);
            uint32_t p10 = __float_as_uint(ap[8]);
            uint32_t p11 = __float_as_uint(ap[8 * 36 + 8]);
            uint32_t p12 = __float_as_uint(ap[12]);
            uint32_t p13 = __float_as_uint(ap[8 * 36 + 12]);
            #pragma unroll
            for (int nf = 0; nf < 8; nf++) {
                int nfg = cg * 8 + nf;
                float4 b = *(const float4*)(Bb + (nfg * 2 + ksh) * 128 + lane * 4);
                mma_tf32(acc[0][nf], p00, p01, p02, p03,
                         __float_as_uint(b.x), __float_as_uint(b.y));
                mma_tf32(acc[0][nf], p10, p11, p12, p13,
                         __float_as_uint(b.z), __float_as_uint(b.w));
                if constexpr (NS == 2) {
                    float4 b1v = *(const float4*)(Bb + 4096 + (nfg * 2 + ksh) * 128 + lane * 4);
                    mma_tf32(acc[1][nf], p00, p01, p02, p03,
                             __float_as_uint(b1v.x), __float_as_uint(b1v.y));
                    mma_tf32(acc[1][nf], p10, p11, p12, p13,
                             __float_as_uint(b1v.z), __float_as_uint(b1v.w));
                }
            }
        }
        __syncthreads();
    }

    int r0 = wr * 16 + (lane >> 2);
    int row0 = m0 + r0, row1 = row0 + 8;
    #pragma unroll
    for (int s = 0; s < NS; s++) {
        #pragma unroll
        for (int nf = 0; nf < 8; nf++) {
            int lc = cg * 64 + nf * 8 + (lane & 3) * 2;
            int col = s * 128 + lc;
            float v0 = acc[s][nf][0] + s_bias[col];
            float v1 = acc[s][nf][1] + s_bias[col + 1];
            float v2 = acc[s][nf][2] + s_bias[col];
            float v3 = acc[s][nf][3] + s_bias[col + 1];
            if (SILU) { v0 = silu_f(v0); v1 = silu_f(v1); v2 = silu_f(v2); v3 = silu_f(v3); }
            if constexpr (HOUT) {
                __half* Ch = (__half*)Cv;
                if (row0 < M)
                    *(uint32_t*)(Ch + (size_t)row0 * ldC + col) = f2h2(v0, v1);
                if (row1 < M)
                    *(uint32_t*)(Ch + (size_t)row1 * ldC + col) = f2h2(v2, v3);
            } else {
                float* C = (float*)Cv;
                if (row0 < M) {
                    if (RES) {
                        float2 r = *(const float2*)(Rsrc + (size_t)row0 * 128 + col);
                        v0 += r.x; v1 += r.y;
                    }
                    *(float2*)(C + (size_t)row0 * ldC + col) = make_float2(v0, v1);
                    if (DUAL) *(float2*)(C2 + (size_t)row0 * ldC2 + col) = make_float2(v0, v1);
                }
                if (row1 < M) {
                    if (RES) {
                        float2 r = *(const float2*)(Rsrc + (size_t)row1 * 128 + col);
                        v2 += r.x; v3 += r.y;
                    }
                    *(float2*)(C + (size_t)row1 * ldC + col) = make_float2(v2, v3);
                    if (DUAL) *(float2*)(C2 + (size_t)row1 * ldC2 + col) = make_float2(v2, v3);
                }
            }
        }
    }
}
#define NODE_SMEM1 42496
#define NODE_SMEM2 75776

// ================= fused edge kernel: all-resident smem (unchanged R15) =================
#define EDGE_SMEM 104960
__global__ void __launch_bounds__(256, 2) mma_edge(
    const int* __restrict__ esrc, const int* __restrict__ edst,
    const float* __restrict__ coords, const __half* __restrict__ P,
    const float* __restrict__ wc, const float* __restrict__ eb2,
    const __half* __restrict__ w2pk, const __half* __restrict__ c1pk,
    const float* __restrict__ cb1, const float* __restrict__ cw2) {
    extern __shared__ char smc[];
    __half* Ah    = (__half*)smc;                 // 128 x 136 halves
    __half* Bw    = (__half*)(smc + 34816);
    __half* Bc    = (__half*)(smc + 67584);
    float* s_gate = (float*)(smc + 100352);
    int* s_src    = (int*)(smc + 101376);
    int* s_dst    = (int*)(smc + 101888);
    float* s_ds   = (float*)(smc + 102400);
    float* s_wc   = (float*)(smc + 102912);
    float* s_eb2  = (float*)(smc + 103424);
    float* s_cb1  = (float*)(smc + 103936);
    float* s_cw2  = (float*)(smc + 104448);
    int tid = threadIdx.x, w = tid >> 5, lane = tid & 31;
    int wr = w & 3, cg = w >> 2;
    uint32_t bw_sm = (uint32_t)__cvta_generic_to_shared(Bw);
    uint32_t bc_sm = (uint32_t)__cvta_generic_to_shared(Bc);
    int ebase = blockIdx.x * 128;

    #pragma unroll
    for (int j = 0; j < 8; j++)
        cp16(bw_sm + (tid + j * 256) * 16, w2pk + (tid + j * 256) * 8);
    #pragma unroll
    for (int j = 0; j < 8; j++)
        cp16(bc_sm + (tid + j * 256) * 16, c1pk + (tid + j * 256) * 8);
    CP_COMMIT();

    if (tid < 128) {
        int e = ebase + tid;
        int s = esrc[e], d = edst[e];
        s_src[tid] = s; s_dst[tid] = d;
        float dx = coords[s * 3 + 0] - coords[d * 3 + 0];
        float dy = coords[s * 3 + 1] - coords[d * 3 + 1];
        float dz = coords[s * 3 + 2] - coords[d * 3 + 2];
        s_ds[tid] = dx * dx + dy * dy + dz * dz;
        s_wc[tid] = wc[tid];
        s_eb2[tid] = eb2[tid];
        s_cb1[tid] = cb1[tid];
        s_cw2[tid] = cw2[tid];
    }
    __syncthreads();

    #pragma unroll
    for (int kb = 0; kb < 4; kb++) {
        #pragma unroll
        for (int i = 0; i < 2; i++) {
            int idx = tid + i * 256;
            int r = idx >> 2, c8 = idx & 3;
            int s = s_src[r], d = s_dst[r];
            float ds = s_ds[r];
            uint4 us = *(const uint4*)(P + (size_t)s * 256 + kb * 32 + c8 * 8);
            uint4 ud = *(const uint4*)(P + (size_t)d * 256 + 128 + kb * 32 + c8 * 8);
            const float* Wv = s_wc + kb * 32 + c8 * 8;
            float4 w0 = *(const float4*)Wv, w1 = *(const float4*)(Wv + 4);
            float2 s0 = __half22float2(*(__half2*)&us.x);
            float2 s1 = __half22float2(*(__half2*)&us.y);
            float2 s2 = __half22float2(*(__half2*)&us.z);
            float2 s3 = __half22float2(*(__half2*)&us.w);
            float2 d0 = __half22float2(*(__half2*)&ud.x);
            float2 d1 = __half22float2(*(__half2*)&ud.y);
            float2 d2 = __half22float2(*(__half2*)&ud.z);
            float2 d3 = __half22float2(*(__half2*)&ud.w);
            uint4 v;
            v.x = f2h2(silu_f(s0.x + d0.x + ds * w0.x), silu_f(s0.y + d0.y + ds * w0.y));
            v.y = f2h2(silu_f(s1.x + d1.x + ds * w0.z), silu_f(s1.y + d1.y + ds * w0.w));
            v.z = f2h2(silu_f(s2.x + d2.x + ds * w1.x), silu_f(s2.y + d2.y + ds * w1.y));
            v.w = f2h2(silu_f(s3.x + d3.x + ds * w1.z), silu_f(s3.y + d3.y + ds * w1.w));
            *(uint4*)(Ah + r * 136 + kb * 32 + c8 * 8) = v;
        }
    }
    CP_WAIT0();
    __syncthreads();

    float acc[2][8][4];
    #pragma unroll
    for (int mf = 0; mf < 2; mf++)
        #pragma unroll
        for (int nf = 0; nf < 8; nf++)
            #pragma unroll
            for (int j = 0; j < 4; j++) acc[mf][nf][j] = 0.f;

    auto gemm_full = [&](const __half* Bb) {
        #pragma unroll
        for (int kb = 0; kb < 4; kb++) {
            uint32_t Areg[2][2][4];
            const __half* ap = Ah + (wr * 32 + (lane >> 2)) * 136 + kb * 32 + (lane & 3) * 2;
            #pragma unroll
            for (int mf = 0; mf < 2; mf++) {
                const __half* base = ap + mf * 16 * 136;
                #pragma unroll
                for (int ks = 0; ks < 2; ks++) {
                    const __half* p = base + ks * 16;
                    Areg[mf][ks][0] = *(const uint32_t*)(p);
                    Areg[mf][ks][1] = *(const uint32_t*)(p + 8 * 136);
                    Areg[mf][ks][2] = *(const uint32_t*)(p + 8);
                    Areg[mf][ks][3] = *(const uint32_t*)(p + 8 * 136 + 8);
                }
            }
            const __half* Bkb = Bb + kb * 4096;
            #pragma unroll
            for (int nf = 0; nf < 8; nf++) {
                uint4 bv = *(const uint4*)(Bkb + ((cg * 8 + nf) * 32 + lane) * 8);
                #pragma unroll
                for (int mf = 0; mf < 2; mf++) {
                    mma_f16(acc[mf][nf], Areg[mf][0][0], Areg[mf][0][1], Areg[mf][0][2], Areg[mf][0][3],
                            bv.x, bv.y);
                    mma_f16(acc[mf][nf], Areg[mf][1][0], Areg[mf][1][1], Areg[mf][1][2], Areg[mf][1][3],
                            bv.z, bv.w);
                }
            }
        }
    };

    gemm_full(Bw);
    __syncthreads();

    int r0 = wr * 32 + (lane >> 2);
    int e0 = ebase + r0;
    #pragma unroll
    for (int mf = 0; mf < 2; mf++) {
        int ea = e0 + mf * 16;
        int ra = r0 + mf * 16;
        #pragma unroll
        for (int nf = 0; nf < 8; nf++) {
            int col = cg * 64 + nf * 8 + (lane & 3) * 2;
            float m0 = silu_f(acc[mf][nf][0] + s_eb2[col]);
            float m1 = silu_f(acc[mf][nf][1] + s_eb2[col + 1]);
            float m2 = silu_f(acc[mf][nf][2] + s_eb2[col]);
            float m3 = silu_f(acc[mf][nf][3] + s_eb2[col + 1]);
            uint32_t h01 = f2h2(m0, m1), h23 = f2h2(m2, m3);
            *(uint32_t*)(g_M + (size_t)ea * 128 + col)       = h01;
            *(uint32_t*)(g_M + (size_t)(ea + 8) * 128 + col) = h23;
            *(uint32_t*)(Ah + ra * 136 + col)       = h01;
            *(uint32_t*)(Ah + (ra + 8) * 136 + col) = h23;
            acc[mf][nf][0] = 0.f; acc[mf][nf][1] = 0.f;
            acc[mf][nf][2] = 0.f; acc[mf][nf][3] = 0.f;
        }
    }
    __syncthreads();

    gemm_full(Bc);

    float gp[4] = {0.f, 0.f, 0.f, 0.f};
    #pragma unroll
    for (int mf = 0; mf < 2; mf++) {
        #pragma unroll
        for (int nf = 0; nf < 8; nf++) {
            int col = cg * 64 + nf * 8 + (lane & 3) * 2;
            gp[mf * 2]     += silu_f(acc[mf][nf][0] + s_cb1[col]) * s_cw2[col]
                            + silu_f(acc[mf][nf][1] + s_cb1[col + 1]) * s_cw2[col + 1];
            gp[mf * 2 + 1] += silu_f(acc[mf][nf][2] + s_cb1[col]) * s_cw2[col]
                            + silu_f(acc[mf][nf][3] + s_cb1[col + 1]) * s_cw2[col + 1];
        }
    }
    #pragma unroll
    for (int j = 0; j < 4; j++) {
        gp[j] += __shfl_xor_sync(0xffffffffu, gp[j], 1);
        gp[j] += __shfl_xor_sync(0xffffffffu, gp[j], 2);
    }
    if ((lane & 3) == 0) {
        int rl = wr * 32 + (lane >> 2);
        s_gate[rl * 2 + cg]        = gp[0];
        s_gate[(rl + 8) * 2 + cg]  = gp[1];
        s_gate[(rl + 16) * 2 + cg] = gp[2];
        s_gate[(rl + 24) * 2 + cg] = gp[3];
    }
    __syncthreads();
    if (tid < 128) {
        float gt = s_gate[tid * 2] + s_gate[tid * 2 + 1];
        int s = s_src[tid], d = s_dst[tid];
        float dx = coords[s * 3 + 0] - coords[d * 3 + 0];
        float dy = coords[s * 3 + 1] - coords[d * 3 + 1];
        float dz = coords[s * 3 + 2] - coords[d * 3 + 2];
        float q = gt * __frsqrt_rn(s_ds[tid] + 1e-8f);
        atomicAdd(&g_shift[d * 3 + 0], dx * q);
        atomicAdd(&g_shift[d * 3 + 1], dy * q);
        atomicAdd(&g_shift[d * 3 + 2], dz * q);
    }
}

// ================= host =================
extern "C" void kernel_launch(void* const* d_in, const int* in_sizes, int n_in,
                              void* d_out, int out_size) {
    const float* z      = (const float*)d_in[0];
    const float* t      = (const float*)d_in[1];
    const float* coords = (const float*)d_in[2];
    const int*   species= (const int*)d_in[3];
    const int*   batch  = (const int*)d_in[4];
    const int*   esrc   = (const int*)d_in[5];
    const int*   edst   = (const int*)d_in[6];
    const float* spemb  = (const float*)d_in[7];
    const float* tmW1   = (const float*)d_in[8];
    const float* tmb1   = (const float*)d_in[9];
    const float* tmW2   = (const float*)d_in[10];
    const float* tmb2   = (const float*)d_in[11];
    const float* neW    = (const float*)d_in[12];
    const float* neb    = (const float*)d_in[13];
    const float* eW1    = (const float*)d_in[14];
    const float* eb1    = (const float*)d_in[15];
    const float* eW2    = (const float*)d_in[16];
    const float* eb2    = (const float*)d_in[17];
    const float* cW1    = (const float*)d_in[18];
    const float* cb1    = (const float*)d_in[19];
    const float* cW2    = (const float*)d_in[20];
    const float* nW1    = (const float*)d_in[21];
    const float* nb1    = (const float*)d_in[22];
    const float* nW2    = (const float*)d_in[23];
    const float* nb2    = (const float*)d_in[24];
    float* out = (float*)d_out;

    float *pX, *pU, *pH, *pPk, *pBiasP;
    __half *pM, *pP, *pPkh;
    cudaGetSymbolAddress((void**)&pX,    g_X);
    cudaGetSymbolAddress((void**)&pP,    g_P);
    cudaGetSymbolAddress((void**)&pU,    g_u);
    cudaGetSymbolAddress((void**)&pH,    g_h);
    cudaGetSymbolAddress((void**)&pM,    g_M);
    cudaGetSymbolAddress((void**)&pPk,   g_packW);
    cudaGetSymbolAddress((void**)&pPkh,  g_packWh);
    cudaGetSymbolAddress((void**)&pBiasP, g_biasP);

    cudaFuncSetAttribute(mma_edge, cudaFuncAttributeMaxDynamicSharedMemorySize, EDGE_SMEM);
    cudaFuncSetAttribute(mma_node<1,1,false,false,true,false,false>,  cudaFuncAttributeMaxDynamicSharedMemorySize, NODE_SMEM1);
    cudaFuncSetAttribute(mma_node<2,0,false,false,false,true,false>,  cudaFuncAttributeMaxDynamicSharedMemorySize, NODE_SMEM2);
    cudaFuncSetAttribute(mma_node<1,2,true,false,false,false,false>,  cudaFuncAttributeMaxDynamicSharedMemorySize, NODE_SMEM1);
    cudaFuncSetAttribute(mma_node<1,0,false,true,true,false,false>,   cudaFuncAttributeMaxDynamicSharedMemorySize, NODE_SMEM1);
    cudaFuncSetAttribute(mma_node<1,0,false,true,false,false,true>,   cudaFuncAttributeMaxDynamicSharedMemorySize, NODE_SMEM1);

    const int MT = (NN + 63) / 64;   // 313

    setup_kernel<<<dim3(1024, 7), 256>>>(eW2, cW1, nW2, nW1, neW, eW1, eb1,
                                         t, tmW1, tmb1, tmW2, tmb2);
    // h0 = [z|sp] @ neW + neb  (dual-store h, X[:, :128])
    mma_node<1, 1, false, false, true, false, false><<<MT, 256, NODE_SMEM1>>>(
        z, spemb, nullptr, species, batch, 128,
        pPk + PK_NE, nullptr, neb, pH, 128, pX, 256, NN, 5, nullptr, nullptr);

    for (int l = 0; l < NL; l++) {
        // P = [h|t] @ Wp  -> fp16 g_P
        mma_node<2, 0, false, false, false, true, false><<<MT, 256, NODE_SMEM2>>>(
            pX, nullptr, nullptr, nullptr, nullptr, 256,
            pPk + PK_WP + (l * 2 + 0) * 32768, pPk + PK_WP + (l * 2 + 1) * 32768,
            pBiasP + l * 256, pP, 256, nullptr, 0, NN, 8, nullptr, nullptr);
        // fused edge: m + gate + shift
        mma_edge<<<NE / 128, 256, EDGE_SMEM>>>(
            esrc, edst, coords, pP,
            eW1 + (size_t)l * 385 * 128 + 256 * 128, eb2 + l * 128,
            pPkh + (size_t)l * 16384, pPkh + (size_t)(NL + l) * 16384,
            cb1 + l * 128, cW2 + l * 128);
        // u = silu([h | sum12 m | t] @ nW1 + nb1)
        mma_node<1, 2, true, false, false, false, false><<<MT, 256, NODE_SMEM1>>>(
            pH, pM, pX + 128, nullptr, nullptr, 0,
            pPk + PK_NW1 + l * 49152, nullptr, nb1 + l * 128,
            pU, 128, nullptr, 0, NN, 12, nullptr, nullptr);
        if (l < NL - 1) {
            // h = h + u @ nW2 + nb2  (dual-store h, X)
            mma_node<1, 0, false, true, true, false, false><<<MT, 256, NODE_SMEM1>>>(
                pU, nullptr, nullptr, nullptr, nullptr, 128,
                pPk + PK_NW2 + l * 16384, nullptr, nb2 + l * 128,
                pH, 128, pX, 256, NN, 4, pH, nullptr);
        } else {
            // final: h -> out[NN*3 + ...], shift -> out[0:NN*3]
            mma_node<1, 0, false, true, false, false, true><<<MT, 256, NODE_SMEM1>>>(
                pU, nullptr, nullptr, nullptr, nullptr, 128,
                pPk + PK_NW2 + l * 16384, nullptr, nb2 + l * 128,
                out + NN * 3, 128, nullptr, 0, NN, 4, pH, out);
        }
    }
}